// round 1
// baseline (speedup 1.0000x reference)
#include <cuda_runtime.h>
#include <math.h>

// Problem constants
#define BATCH 2
#define SEQ   2048
#define DMODEL 1024
#define HEADS 16
#define DKH   64
#define DFF   4096
#define ROWS  (BATCH * SEQ)   // 4096

// ---------------- scratch (static device globals; no allocation) -------------
__device__ float g_q [ROWS * DMODEL];
__device__ float g_k [ROWS * DMODEL];
__device__ float g_v [ROWS * DMODEL];
__device__ float g_a [ROWS * DMODEL];
__device__ float g_o [ROWS * DMODEL];
__device__ float g_x1[ROWS * DMODEL];
__device__ float g_x2[ROWS * DMODEL];
__device__ float g_ff[(size_t)ROWS * DFF];

// =============================================================================
// GEMM:  C[M,N] = A[M,K] * B[N,K]^T + bias[N]   (optional ReLU)
// 128x128 block tile, K-tile 16, 256 threads, 8x8 strided micro-tile.
// Conflict-free frag loads: stride 17 -> (tx*17) mod 32 bijective over 16 lanes.
// =============================================================================
__global__ __launch_bounds__(256) void gemm_nt(
    const float* __restrict__ A, const float* __restrict__ B,
    const float* __restrict__ bias, float* __restrict__ C,
    int M, int N, int K, int relu)
{
    __shared__ float As[128 * 17];
    __shared__ float Bs[128 * 17];

    const int tid = threadIdx.x;
    const int tx = tid & 15;
    const int ty = tid >> 4;
    const int m0 = blockIdx.y * 128;
    const int n0 = blockIdx.x * 128;

    const int lr = tid >> 2;          // 0..63  (loader row)
    const int lk = (tid & 3) << 2;    // 0,4,8,12 (loader k offset)

    const float* Ap = A + (size_t)(m0 + lr) * K + lk;
    const float* Bp = B + (size_t)(n0 + lr) * K + lk;

    float acc[8][8];
#pragma unroll
    for (int i = 0; i < 8; i++)
#pragma unroll
        for (int j = 0; j < 8; j++) acc[i][j] = 0.f;

    // prefetch tile 0
    float4 pa0 = *(const float4*)(Ap);
    float4 pa1 = *(const float4*)(Ap + (size_t)64 * K);
    float4 pb0 = *(const float4*)(Bp);
    float4 pb1 = *(const float4*)(Bp + (size_t)64 * K);

    for (int k0 = 0; k0 < K; k0 += 16) {
        // store prefetched tile to smem
        As[(lr     ) * 17 + lk + 0] = pa0.x;
        As[(lr     ) * 17 + lk + 1] = pa0.y;
        As[(lr     ) * 17 + lk + 2] = pa0.z;
        As[(lr     ) * 17 + lk + 3] = pa0.w;
        As[(lr + 64) * 17 + lk + 0] = pa1.x;
        As[(lr + 64) * 17 + lk + 1] = pa1.y;
        As[(lr + 64) * 17 + lk + 2] = pa1.z;
        As[(lr + 64) * 17 + lk + 3] = pa1.w;
        Bs[(lr     ) * 17 + lk + 0] = pb0.x;
        Bs[(lr     ) * 17 + lk + 1] = pb0.y;
        Bs[(lr     ) * 17 + lk + 2] = pb0.z;
        Bs[(lr     ) * 17 + lk + 3] = pb0.w;
        Bs[(lr + 64) * 17 + lk + 0] = pb1.x;
        Bs[(lr + 64) * 17 + lk + 1] = pb1.y;
        Bs[(lr + 64) * 17 + lk + 2] = pb1.z;
        Bs[(lr + 64) * 17 + lk + 3] = pb1.w;
        __syncthreads();

        if (k0 + 16 < K) {
            pa0 = *(const float4*)(Ap + k0 + 16);
            pa1 = *(const float4*)(Ap + (size_t)64 * K + k0 + 16);
            pb0 = *(const float4*)(Bp + k0 + 16);
            pb1 = *(const float4*)(Bp + (size_t)64 * K + k0 + 16);
        }

#pragma unroll
        for (int kk = 0; kk < 16; kk++) {
            float a[8], b[8];
#pragma unroll
            for (int i = 0; i < 8; i++) a[i] = As[(ty + 16 * i) * 17 + kk];
#pragma unroll
            for (int j = 0; j < 8; j++) b[j] = Bs[(tx + 16 * j) * 17 + kk];
#pragma unroll
            for (int i = 0; i < 8; i++)
#pragma unroll
                for (int j = 0; j < 8; j++)
                    acc[i][j] = fmaf(a[i], b[j], acc[i][j]);
        }
        __syncthreads();
    }

    float bv[8];
#pragma unroll
    for (int j = 0; j < 8; j++) bv[j] = bias[n0 + tx + 16 * j];

#pragma unroll
    for (int i = 0; i < 8; i++) {
        const int row = m0 + ty + 16 * i;
        float* Crow = C + (size_t)row * N + n0;
#pragma unroll
        for (int j = 0; j < 8; j++) {
            float vv = acc[i][j] + bv[j];
            if (relu) vv = fmaxf(vv, 0.f);
            Crow[tx + 16 * j] = vv;
        }
    }
}

// =============================================================================
// Flash attention, fp32. Bq=128, Bkv=64, DK=64, online softmax.
// Heads are column slices of [rows, 1024] Q/K/V buffers.
// =============================================================================
__global__ __launch_bounds__(256) void flash_attn(
    const float* __restrict__ Qg, const float* __restrict__ Kg,
    const float* __restrict__ Vg, float* __restrict__ Og,
    int qlen, int kvlen, int causal)
{
    extern __shared__ float sm[];
    float* Qs = sm;                 // 128 x 65
    float* Ks = Qs + 128 * 65;      // 64 x 65
    float* Vs = Ks + 64 * 65;       // 64 x 65
    float* Ps = Vs + 64 * 65;       // 128 x 65

    const int tid = threadIdx.x;
    const int tx = tid & 15;
    const int ty = tid >> 4;
    const int b  = blockIdx.z;
    const int h  = blockIdx.y;
    const int q0 = blockIdx.x * 128;

    const float* Qb = Qg + (size_t)b * qlen  * DMODEL + h * DKH;
    const float* Kb = Kg + (size_t)b * kvlen * DMODEL + h * DKH;
    const float* Vb = Vg + (size_t)b * kvlen * DMODEL + h * DKH;

    // load Q tile, pre-scaled by 1/sqrt(64)
    for (int idx = tid; idx < 128 * 16; idx += 256) {
        const int r  = idx >> 4;
        const int fq = (idx & 15) << 2;
        float4 qv = *(const float4*)(Qb + (size_t)(q0 + r) * DMODEL + fq);
        Qs[r * 65 + fq + 0] = qv.x * 0.125f;
        Qs[r * 65 + fq + 1] = qv.y * 0.125f;
        Qs[r * 65 + fq + 2] = qv.z * 0.125f;
        Qs[r * 65 + fq + 3] = qv.w * 0.125f;
    }

    float m_i[8], l_i[8], o[8][4];
#pragma unroll
    for (int i = 0; i < 8; i++) {
        m_i[i] = -1e30f;
        l_i[i] = 0.f;
#pragma unroll
        for (int j = 0; j < 4; j++) o[i][j] = 0.f;
    }

    const int kv_end = causal ? min(kvlen, q0 + 128) : kvlen;

    for (int kv0 = 0; kv0 < kv_end; kv0 += 64) {
        __syncthreads();  // protect Ks/Vs/Ps from previous iteration readers
        for (int idx = tid; idx < 64 * 16; idx += 256) {
            const int r  = idx >> 4;
            const int fq = (idx & 15) << 2;
            float4 kv4 = *(const float4*)(Kb + (size_t)(kv0 + r) * DMODEL + fq);
            Ks[r * 65 + fq + 0] = kv4.x;
            Ks[r * 65 + fq + 1] = kv4.y;
            Ks[r * 65 + fq + 2] = kv4.z;
            Ks[r * 65 + fq + 3] = kv4.w;
            float4 vv4 = *(const float4*)(Vb + (size_t)(kv0 + r) * DMODEL + fq);
            Vs[r * 65 + fq + 0] = vv4.x;
            Vs[r * 65 + fq + 1] = vv4.y;
            Vs[r * 65 + fq + 2] = vv4.z;
            Vs[r * 65 + fq + 3] = vv4.w;
        }
        __syncthreads();

        // S = Q * K^T   (scaled already)
        float s[8][4];
#pragma unroll
        for (int i = 0; i < 8; i++)
#pragma unroll
            for (int j = 0; j < 4; j++) s[i][j] = 0.f;

#pragma unroll 16
        for (int kk = 0; kk < 64; kk++) {
            float a[8], bb[4];
#pragma unroll
            for (int i = 0; i < 8; i++) a[i] = Qs[(ty + 16 * i) * 65 + kk];
#pragma unroll
            for (int j = 0; j < 4; j++) bb[j] = Ks[(tx + 16 * j) * 65 + kk];
#pragma unroll
            for (int i = 0; i < 8; i++)
#pragma unroll
                for (int j = 0; j < 4; j++)
                    s[i][j] = fmaf(a[i], bb[j], s[i][j]);
        }

        if (causal) {
#pragma unroll
            for (int i = 0; i < 8; i++)
#pragma unroll
                for (int j = 0; j < 4; j++)
                    if (kv0 + tx + 16 * j > q0 + ty + 16 * i) s[i][j] = -1e30f;
        }

        // online softmax update (rows of a ty-group live in one 16-lane half)
#pragma unroll
        for (int i = 0; i < 8; i++) {
            float mt = s[i][0];
#pragma unroll
            for (int j = 1; j < 4; j++) mt = fmaxf(mt, s[i][j]);
#pragma unroll
            for (int off = 1; off < 16; off <<= 1)
                mt = fmaxf(mt, __shfl_xor_sync(0xffffffffu, mt, off));
            const float mn = fmaxf(m_i[i], mt);
            const float corr = __expf(m_i[i] - mn);
            m_i[i] = mn;
            float rs = 0.f;
#pragma unroll
            for (int j = 0; j < 4; j++) {
                const float p = __expf(s[i][j] - mn);
                Ps[(ty + 16 * i) * 65 + tx + 16 * j] = p;
                rs += p;
            }
#pragma unroll
            for (int off = 1; off < 16; off <<= 1)
                rs += __shfl_xor_sync(0xffffffffu, rs, off);
            l_i[i] = l_i[i] * corr + rs;
#pragma unroll
            for (int j = 0; j < 4; j++) o[i][j] *= corr;
        }
        __syncthreads();  // Ps visible

        // O += P * V
#pragma unroll 16
        for (int kk = 0; kk < 64; kk++) {
            float a2[8], b2[4];
#pragma unroll
            for (int i = 0; i < 8; i++) a2[i] = Ps[(ty + 16 * i) * 65 + kk];
#pragma unroll
            for (int j = 0; j < 4; j++) b2[j] = Vs[kk * 65 + tx + 16 * j];
#pragma unroll
            for (int i = 0; i < 8; i++)
#pragma unroll
                for (int j = 0; j < 4; j++)
                    o[i][j] = fmaf(a2[i], b2[j], o[i][j]);
        }
    }

    // normalize + write
#pragma unroll
    for (int i = 0; i < 8; i++) {
        const float inv = 1.f / l_i[i];
        const int r = q0 + ty + 16 * i;
        float* Orow = Og + ((size_t)b * qlen + r) * DMODEL + h * DKH;
#pragma unroll
        for (int j = 0; j < 4; j++) Orow[tx + 16 * j] = o[i][j] * inv;
    }
}

// =============================================================================
// out = LayerNorm(x + y) * g + be      (one block per row of 1024)
// =============================================================================
__global__ __launch_bounds__(256) void add_ln(
    const float* __restrict__ X, const float* __restrict__ Y,
    const float* __restrict__ g, const float* __restrict__ be,
    float* __restrict__ Out)
{
    __shared__ float red[8];
    const int row = blockIdx.x;
    const int tid = threadIdx.x;
    const float* xr = X + (size_t)row * DMODEL;
    const float* yr = Y + (size_t)row * DMODEL;

    float v[4];
    float s = 0.f;
#pragma unroll
    for (int c = 0; c < 4; c++) {
        const int idx = tid + 256 * c;
        v[c] = xr[idx] + yr[idx];
        s += v[c];
    }
    // block reduce sum
#pragma unroll
    for (int off = 16; off >= 1; off >>= 1) s += __shfl_xor_sync(0xffffffffu, s, off);
    if ((tid & 31) == 0) red[tid >> 5] = s;
    __syncthreads();
    if (tid < 32) {
        float t = (tid < 8) ? red[tid] : 0.f;
#pragma unroll
        for (int off = 4; off >= 1; off >>= 1) t += __shfl_xor_sync(0xffffffffu, t, off);
        if (tid == 0) red[0] = t;
    }
    __syncthreads();
    const float mu = red[0] * (1.f / DMODEL);
    __syncthreads();

    float sq = 0.f;
#pragma unroll
    for (int c = 0; c < 4; c++) {
        const float d = v[c] - mu;
        sq += d * d;
    }
#pragma unroll
    for (int off = 16; off >= 1; off >>= 1) sq += __shfl_xor_sync(0xffffffffu, sq, off);
    if ((tid & 31) == 0) red[tid >> 5] = sq;
    __syncthreads();
    if (tid < 32) {
        float t = (tid < 8) ? red[tid] : 0.f;
#pragma unroll
        for (int off = 4; off >= 1; off >>= 1) t += __shfl_xor_sync(0xffffffffu, t, off);
        if (tid == 0) red[0] = t;
    }
    __syncthreads();
    const float rstd = rsqrtf(red[0] * (1.f / DMODEL) + 1e-5f);

    float* orow = Out + (size_t)row * DMODEL;
#pragma unroll
    for (int c = 0; c < 4; c++) {
        const int idx = tid + 256 * c;
        orow[idx] = (v[c] - mu) * rstd * g[idx] + be[idx];
    }
}

// =============================================================================
// Launch
// =============================================================================
extern "C" void kernel_launch(void* const* d_in, const int* in_sizes, int n_in,
                              void* d_out, int out_size)
{
    (void)in_sizes; (void)n_in; (void)out_size;
    const float* x     = (const float*)d_in[0];
    const float* enc   = (const float*)d_in[1];
    // d_in[2] src_mask (all ones), d_in[3] tgt_mask (causal tril): applied analytically
    const float* Wq1 = (const float*)d_in[4];  const float* bq1 = (const float*)d_in[5];
    const float* Wk1 = (const float*)d_in[6];  const float* bk1 = (const float*)d_in[7];
    const float* Wv1 = (const float*)d_in[8];  const float* bv1 = (const float*)d_in[9];
    const float* Wo1 = (const float*)d_in[10]; const float* bo1 = (const float*)d_in[11];
    const float* Wq2 = (const float*)d_in[12]; const float* bq2 = (const float*)d_in[13];
    const float* Wk2 = (const float*)d_in[14]; const float* bk2 = (const float*)d_in[15];
    const float* Wv2 = (const float*)d_in[16]; const float* bv2 = (const float*)d_in[17];
    const float* Wo2 = (const float*)d_in[18]; const float* bo2 = (const float*)d_in[19];
    const float* Wf1 = (const float*)d_in[20]; const float* bf1 = (const float*)d_in[21];
    const float* Wf2 = (const float*)d_in[22]; const float* bf2 = (const float*)d_in[23];
    const float* g1  = (const float*)d_in[24]; const float* be1 = (const float*)d_in[25];
    const float* g2  = (const float*)d_in[26]; const float* be2 = (const float*)d_in[27];
    const float* g3  = (const float*)d_in[28]; const float* be3 = (const float*)d_in[29];
    float* out = (float*)d_out;

    float *q, *k, *v, *a, *o, *x1, *x2, *ff;
    cudaGetSymbolAddress((void**)&q,  g_q);
    cudaGetSymbolAddress((void**)&k,  g_k);
    cudaGetSymbolAddress((void**)&v,  g_v);
    cudaGetSymbolAddress((void**)&a,  g_a);
    cudaGetSymbolAddress((void**)&o,  g_o);
    cudaGetSymbolAddress((void**)&x1, g_x1);
    cudaGetSymbolAddress((void**)&x2, g_x2);
    cudaGetSymbolAddress((void**)&ff, g_ff);

    const int FLASH_SMEM = (128 * 65 + 64 * 65 + 64 * 65 + 128 * 65) * 4;  // 99840 B
    cudaFuncSetAttribute(flash_attn, cudaFuncAttributeMaxDynamicSharedMemorySize, FLASH_SMEM);

    const dim3 gProj(DMODEL / 128, ROWS / 128);   // (8, 32)
    const dim3 gFF1 (DFF    / 128, ROWS / 128);   // (32, 32)
    const dim3 gAttn(SEQ / 128, HEADS, BATCH);    // (16, 16, 2)

    // ---- self attention ----
    gemm_nt<<<gProj, 256>>>(x, Wq1, bq1, q, ROWS, DMODEL, DMODEL, 0);
    gemm_nt<<<gProj, 256>>>(x, Wk1, bk1, k, ROWS, DMODEL, DMODEL, 0);
    gemm_nt<<<gProj, 256>>>(x, Wv1, bv1, v, ROWS, DMODEL, DMODEL, 0);
    flash_attn<<<gAttn, 256, FLASH_SMEM>>>(q, k, v, a, SEQ, SEQ, 1);
    gemm_nt<<<gProj, 256>>>(a, Wo1, bo1, o, ROWS, DMODEL, DMODEL, 0);
    add_ln<<<ROWS, 256>>>(x, o, g1, be1, x1);

    // ---- cross attention ----
    gemm_nt<<<gProj, 256>>>(x1,  Wq2, bq2, q, ROWS, DMODEL, DMODEL, 0);
    gemm_nt<<<gProj, 256>>>(enc, Wk2, bk2, k, ROWS, DMODEL, DMODEL, 0);
    gemm_nt<<<gProj, 256>>>(enc, Wv2, bv2, v, ROWS, DMODEL, DMODEL, 0);
    flash_attn<<<gAttn, 256, FLASH_SMEM>>>(q, k, v, a, SEQ, SEQ, 0);
    gemm_nt<<<gProj, 256>>>(a, Wo2, bo2, o, ROWS, DMODEL, DMODEL, 0);
    add_ln<<<ROWS, 256>>>(x1, o, g2, be2, x2);

    // ---- FFN ----
    gemm_nt<<<gFF1, 256>>>(x2, Wf1, bf1, ff, ROWS, DFF, DMODEL, 1);
    gemm_nt<<<gProj, 256>>>(ff, Wf2, bf2, o, ROWS, DMODEL, DFF, 0);
    add_ln<<<ROWS, 256>>>(x2, o, g3, be3, out);
}

// round 4
// speedup vs baseline: 1.8570x; 1.8570x over previous
#include <cuda_runtime.h>
#include <math.h>
#include <stdint.h>

// Problem constants
#define BATCH 2
#define SEQ   2048
#define DMODEL 1024
#define HEADS 16
#define DKH   64
#define DFF   4096
#define ROWS  (BATCH * SEQ)   // 4096

// ---------------- scratch (static device globals; no allocation) -------------
__device__ float g_q [ROWS * DMODEL];
__device__ float g_k [ROWS * DMODEL];
__device__ float g_v [ROWS * DMODEL];
__device__ float g_a [ROWS * DMODEL];
__device__ float g_o [ROWS * DMODEL];
__device__ float g_x1[ROWS * DMODEL];
__device__ float g_x2[ROWS * DMODEL];
__device__ float g_ff[(size_t)ROWS * DFF];

// =============================================================================
// TF32 tensor-core GEMM:  C[M,N] = A[M,K] * B[N,K]^T + bias[N]  (optional ReLU)
// 128x128 block tile, K-tile 32, 256 threads (8 warps, 2m x 4n),
// warp tile 64x32 -> 4x4 mma.m16n8k8.tf32. Smem row stride 36 words
// => conflict-free ldmatrix. cp.async double buffering.
// =============================================================================
#define KT     32
#define LDS_S  36                    // padded stride (words) per 32-word row
#define TILE_W (128 * LDS_S)         // words per tile

__device__ __forceinline__ unsigned smem_u32(const void* p) {
    return (unsigned)__cvta_generic_to_shared(p);
}

__global__ __launch_bounds__(256) void gemm_tf32(
    const float* __restrict__ A, const float* __restrict__ B,
    const float* __restrict__ bias, float* __restrict__ C,
    int M, int N, int K, int relu)
{
    extern __shared__ float sh[];
    float* As = sh;                   // 2 stages
    float* Bs = sh + 2 * TILE_W;      // 2 stages

    const int tid  = threadIdx.x;
    const int lane = tid & 31;
    const int w    = tid >> 5;
    const int wm   = w & 1;           // 0..1
    const int wn   = w >> 1;          // 0..3
    const int m0 = blockIdx.y * 128;
    const int n0 = blockIdx.x * 128;

    float acc[4][4][4];
#pragma unroll
    for (int mi = 0; mi < 4; mi++)
#pragma unroll
        for (int ni = 0; ni < 4; ni++)
#pragma unroll
            for (int r = 0; r < 4; r++) acc[mi][ni][r] = 0.f;

    // loader mapping: 1024 float4 per tile, 4 per thread
    const int lrow0 = tid >> 3;       // row advances by 32 per chunk
    const int lc4   = (tid & 7) << 2; // word offset 0..28 step 4

    auto load_tile = [&](int st, int k0) {
        const float* Asrc = A + (size_t)(m0 + lrow0) * K + k0 + lc4;
        const float* Bsrc = B + (size_t)(n0 + lrow0) * K + k0 + lc4;
        unsigned Adst = smem_u32(As + st * TILE_W + lrow0 * LDS_S + lc4);
        unsigned Bdst = smem_u32(Bs + st * TILE_W + lrow0 * LDS_S + lc4);
#pragma unroll
        for (int i = 0; i < 4; i++) {
            asm volatile("cp.async.cg.shared.global [%0], [%1], 16;\n"
                         :: "r"(Adst + i * 32 * LDS_S * 4),
                            "l"(Asrc + (size_t)i * 32 * K));
            asm volatile("cp.async.cg.shared.global [%0], [%1], 16;\n"
                         :: "r"(Bdst + i * 32 * LDS_S * 4),
                            "l"(Bsrc + (size_t)i * 32 * K));
        }
    };

    // ldmatrix per-thread row mappings (constant across k)
    const int a_row = wm * 64 + (lane & 7) + ((lane >> 3) & 1) * 8;  // + mi*16
    const int a_cw  = (lane >> 4) * 4;                               // + ks*8
    const int b_row = wn * 32 + (lane & 7) + (lane >> 4) * 8;        // + p*16
    const int b_cw  = ((lane >> 3) & 1) * 4;                         // + ks*8

    load_tile(0, 0);
    asm volatile("cp.async.commit_group;\n");

    const int nk = K >> 5;
    for (int kt = 0; kt < nk; kt++) {
        const int st = kt & 1;
        if (kt + 1 < nk) {
            load_tile((kt + 1) & 1, (kt + 1) << 5);
            asm volatile("cp.async.commit_group;\n");
            asm volatile("cp.async.wait_group 1;\n");
        } else {
            asm volatile("cp.async.wait_group 0;\n");
        }
        __syncthreads();

        const float* Ab = As + st * TILE_W;
        const float* Bb = Bs + st * TILE_W;

#pragma unroll
        for (int ks = 0; ks < 4; ks++) {
            uint32_t af[4][4];
            uint32_t bf[4][2];
#pragma unroll
            for (int mi = 0; mi < 4; mi++) {
                unsigned ad = smem_u32(Ab + (a_row + mi * 16) * LDS_S + ks * 8 + a_cw);
                asm volatile(
                    "ldmatrix.sync.aligned.m8n8.x4.shared.b16 {%0,%1,%2,%3}, [%4];\n"
                    : "=r"(af[mi][0]), "=r"(af[mi][1]), "=r"(af[mi][2]), "=r"(af[mi][3])
                    : "r"(ad));
            }
#pragma unroll
            for (int p = 0; p < 2; p++) {
                unsigned bd = smem_u32(Bb + (b_row + p * 16) * LDS_S + ks * 8 + b_cw);
                asm volatile(
                    "ldmatrix.sync.aligned.m8n8.x4.shared.b16 {%0,%1,%2,%3}, [%4];\n"
                    : "=r"(bf[2 * p][0]), "=r"(bf[2 * p][1]),
                      "=r"(bf[2 * p + 1][0]), "=r"(bf[2 * p + 1][1])
                    : "r"(bd));
            }
            // round to tf32 (avoid truncation bias)
#pragma unroll
            for (int mi = 0; mi < 4; mi++)
#pragma unroll
                for (int r = 0; r < 4; r++)
                    asm volatile("cvt.rna.tf32.f32 %0, %0;\n" : "+r"(af[mi][r]));
#pragma unroll
            for (int ni = 0; ni < 4; ni++)
#pragma unroll
                for (int r = 0; r < 2; r++)
                    asm volatile("cvt.rna.tf32.f32 %0, %0;\n" : "+r"(bf[ni][r]));

#pragma unroll
            for (int mi = 0; mi < 4; mi++)
#pragma unroll
                for (int ni = 0; ni < 4; ni++) {
                    asm volatile(
                        "mma.sync.aligned.m16n8k8.row.col.f32.tf32.tf32.f32 "
                        "{%0,%1,%2,%3}, {%4,%5,%6,%7}, {%8,%9}, {%0,%1,%2,%3};\n"
                        : "+f"(acc[mi][ni][0]), "+f"(acc[mi][ni][1]),
                          "+f"(acc[mi][ni][2]), "+f"(acc[mi][ni][3])
                        : "r"(af[mi][0]), "r"(af[mi][1]), "r"(af[mi][2]), "r"(af[mi][3]),
                          "r"(bf[ni][0]), "r"(bf[ni][1]));
                }
        }
        __syncthreads();
    }

    // epilogue: c0,c1 at (row, 2c),(row, 2c+1); c2,c3 at row+8
#pragma unroll
    for (int mi = 0; mi < 4; mi++) {
        const int row = m0 + wm * 64 + mi * 16 + (lane >> 2);
#pragma unroll
        for (int ni = 0; ni < 4; ni++) {
            const int col = n0 + wn * 32 + ni * 8 + 2 * (lane & 3);
            const float bv0 = bias[col], bv1 = bias[col + 1];
            float v0 = acc[mi][ni][0] + bv0;
            float v1 = acc[mi][ni][1] + bv1;
            float v2 = acc[mi][ni][2] + bv0;
            float v3 = acc[mi][ni][3] + bv1;
            if (relu) {
                v0 = fmaxf(v0, 0.f); v1 = fmaxf(v1, 0.f);
                v2 = fmaxf(v2, 0.f); v3 = fmaxf(v3, 0.f);
            }
            *(float2*)(C + (size_t)row * N + col)       = make_float2(v0, v1);
            *(float2*)(C + (size_t)(row + 8) * N + col) = make_float2(v2, v3);
        }
    }
}

// =============================================================================
// Flash attention, fp32. Bq=128, Bkv=64, DK=64, online softmax.
// =============================================================================
__global__ __launch_bounds__(256) void flash_attn(
    const float* __restrict__ Qg, const float* __restrict__ Kg,
    const float* __restrict__ Vg, float* __restrict__ Og,
    int qlen, int kvlen, int causal)
{
    extern __shared__ float sm[];
    float* Qs = sm;                 // 128 x 65
    float* Ks = Qs + 128 * 65;      // 64 x 65
    float* Vs = Ks + 64 * 65;       // 64 x 65
    float* Ps = Vs + 64 * 65;       // 128 x 65

    const int tid = threadIdx.x;
    const int tx = tid & 15;
    const int ty = tid >> 4;
    const int b  = blockIdx.z;
    const int h  = blockIdx.y;
    const int q0 = blockIdx.x * 128;

    const float* Qb = Qg + (size_t)b * qlen  * DMODEL + h * DKH;
    const float* Kb = Kg + (size_t)b * kvlen * DMODEL + h * DKH;
    const float* Vb = Vg + (size_t)b * kvlen * DMODEL + h * DKH;

    for (int idx = tid; idx < 128 * 16; idx += 256) {
        const int r  = idx >> 4;
        const int fq = (idx & 15) << 2;
        float4 qv = *(const float4*)(Qb + (size_t)(q0 + r) * DMODEL + fq);
        Qs[r * 65 + fq + 0] = qv.x * 0.125f;
        Qs[r * 65 + fq + 1] = qv.y * 0.125f;
        Qs[r * 65 + fq + 2] = qv.z * 0.125f;
        Qs[r * 65 + fq + 3] = qv.w * 0.125f;
    }

    float m_i[8], l_i[8], o[8][4];
#pragma unroll
    for (int i = 0; i < 8; i++) {
        m_i[i] = -1e30f;
        l_i[i] = 0.f;
#pragma unroll
        for (int j = 0; j < 4; j++) o[i][j] = 0.f;
    }

    const int kv_end = causal ? min(kvlen, q0 + 128) : kvlen;

    for (int kv0 = 0; kv0 < kv_end; kv0 += 64) {
        __syncthreads();
        for (int idx = tid; idx < 64 * 16; idx += 256) {
            const int r  = idx >> 4;
            const int fq = (idx & 15) << 2;
            float4 kv4 = *(const float4*)(Kb + (size_t)(kv0 + r) * DMODEL + fq);
            Ks[r * 65 + fq + 0] = kv4.x;
            Ks[r * 65 + fq + 1] = kv4.y;
            Ks[r * 65 + fq + 2] = kv4.z;
            Ks[r * 65 + fq + 3] = kv4.w;
            float4 vv4 = *(const float4*)(Vb + (size_t)(kv0 + r) * DMODEL + fq);
            Vs[r * 65 + fq + 0] = vv4.x;
            Vs[r * 65 + fq + 1] = vv4.y;
            Vs[r * 65 + fq + 2] = vv4.z;
            Vs[r * 65 + fq + 3] = vv4.w;
        }
        __syncthreads();

        float s[8][4];
#pragma unroll
        for (int i = 0; i < 8; i++)
#pragma unroll
            for (int j = 0; j < 4; j++) s[i][j] = 0.f;

#pragma unroll 16
        for (int kk = 0; kk < 64; kk++) {
            float a[8], bb[4];
#pragma unroll
            for (int i = 0; i < 8; i++) a[i] = Qs[(ty + 16 * i) * 65 + kk];
#pragma unroll
            for (int j = 0; j < 4; j++) bb[j] = Ks[(tx + 16 * j) * 65 + kk];
#pragma unroll
            for (int i = 0; i < 8; i++)
#pragma unroll
                for (int j = 0; j < 4; j++)
                    s[i][j] = fmaf(a[i], bb[j], s[i][j]);
        }

        if (causal) {
#pragma unroll
            for (int i = 0; i < 8; i++)
#pragma unroll
                for (int j = 0; j < 4; j++)
                    if (kv0 + tx + 16 * j > q0 + ty + 16 * i) s[i][j] = -1e30f;
        }

#pragma unroll
        for (int i = 0; i < 8; i++) {
            float mt = s[i][0];
#pragma unroll
            for (int j = 1; j < 4; j++) mt = fmaxf(mt, s[i][j]);
#pragma unroll
            for (int off = 1; off < 16; off <<= 1)
                mt = fmaxf(mt, __shfl_xor_sync(0xffffffffu, mt, off));
            const float mn = fmaxf(m_i[i], mt);
            const float corr = __expf(m_i[i] - mn);
            m_i[i] = mn;
            float rs = 0.f;
#pragma unroll
            for (int j = 0; j < 4; j++) {
                const float p = __expf(s[i][j] - mn);
                Ps[(ty + 16 * i) * 65 + tx + 16 * j] = p;
                rs += p;
            }
#pragma unroll
            for (int off = 1; off < 16; off <<= 1)
                rs += __shfl_xor_sync(0xffffffffu, rs, off);
            l_i[i] = l_i[i] * corr + rs;
#pragma unroll
            for (int j = 0; j < 4; j++) o[i][j] *= corr;
        }
        __syncthreads();

#pragma unroll 16
        for (int kk = 0; kk < 64; kk++) {
            float a2[8], b2[4];
#pragma unroll
            for (int i = 0; i < 8; i++) a2[i] = Ps[(ty + 16 * i) * 65 + kk];
#pragma unroll
            for (int j = 0; j < 4; j++) b2[j] = Vs[kk * 65 + tx + 16 * j];
#pragma unroll
            for (int i = 0; i < 8; i++)
#pragma unroll
                for (int j = 0; j < 4; j++)
                    o[i][j] = fmaf(a2[i], b2[j], o[i][j]);
        }
    }

#pragma unroll
    for (int i = 0; i < 8; i++) {
        const float inv = 1.f / l_i[i];
        const int r = q0 + ty + 16 * i;
        float* Orow = Og + ((size_t)b * qlen + r) * DMODEL + h * DKH;
#pragma unroll
        for (int j = 0; j < 4; j++) Orow[tx + 16 * j] = o[i][j] * inv;
    }
}

// =============================================================================
// out = LayerNorm(x + y) * g + be      (one block per row of 1024)
// =============================================================================
__global__ __launch_bounds__(256) void add_ln(
    const float* __restrict__ X, const float* __restrict__ Y,
    const float* __restrict__ g, const float* __restrict__ be,
    float* __restrict__ Out)
{
    __shared__ float red[8];
    const int row = blockIdx.x;
    const int tid = threadIdx.x;
    const float* xr = X + (size_t)row * DMODEL;
    const float* yr = Y + (size_t)row * DMODEL;

    float v[4];
    float s = 0.f;
#pragma unroll
    for (int c = 0; c < 4; c++) {
        const int idx = tid + 256 * c;
        v[c] = xr[idx] + yr[idx];
        s += v[c];
    }
#pragma unroll
    for (int off = 16; off >= 1; off >>= 1) s += __shfl_xor_sync(0xffffffffu, s, off);
    if ((tid & 31) == 0) red[tid >> 5] = s;
    __syncthreads();
    if (tid < 32) {
        float t = (tid < 8) ? red[tid] : 0.f;
#pragma unroll
        for (int off = 4; off >= 1; off >>= 1) t += __shfl_xor_sync(0xffffffffu, t, off);
        if (tid == 0) red[0] = t;
    }
    __syncthreads();
    const float mu = red[0] * (1.f / DMODEL);
    __syncthreads();

    float sq = 0.f;
#pragma unroll
    for (int c = 0; c < 4; c++) {
        const float d = v[c] - mu;
        sq += d * d;
    }
#pragma unroll
    for (int off = 16; off >= 1; off >>= 1) sq += __shfl_xor_sync(0xffffffffu, sq, off);
    if ((tid & 31) == 0) red[tid >> 5] = sq;
    __syncthreads();
    if (tid < 32) {
        float t = (tid < 8) ? red[tid] : 0.f;
#pragma unroll
        for (int off = 4; off >= 1; off >>= 1) t += __shfl_xor_sync(0xffffffffu, t, off);
        if (tid == 0) red[0] = t;
    }
    __syncthreads();
    const float rstd = rsqrtf(red[0] * (1.f / DMODEL) + 1e-5f);

    float* orow = Out + (size_t)row * DMODEL;
#pragma unroll
    for (int c = 0; c < 4; c++) {
        const int idx = tid + 256 * c;
        orow[idx] = (v[c] - mu) * rstd * g[idx] + be[idx];
    }
}

// =============================================================================
// Launch
// =============================================================================
extern "C" void kernel_launch(void* const* d_in, const int* in_sizes, int n_in,
                              void* d_out, int out_size)
{
    (void)in_sizes; (void)n_in; (void)out_size;
    const float* x     = (const float*)d_in[0];
    const float* enc   = (const float*)d_in[1];
    const float* Wq1 = (const float*)d_in[4];  const float* bq1 = (const float*)d_in[5];
    const float* Wk1 = (const float*)d_in[6];  const float* bk1 = (const float*)d_in[7];
    const float* Wv1 = (const float*)d_in[8];  const float* bv1 = (const float*)d_in[9];
    const float* Wo1 = (const float*)d_in[10]; const float* bo1 = (const float*)d_in[11];
    const float* Wq2 = (const float*)d_in[12]; const float* bq2 = (const float*)d_in[13];
    const float* Wk2 = (const float*)d_in[14]; const float* bk2 = (const float*)d_in[15];
    const float* Wv2 = (const float*)d_in[16]; const float* bv2 = (const float*)d_in[17];
    const float* Wo2 = (const float*)d_in[18]; const float* bo2 = (const float*)d_in[19];
    const float* Wf1 = (const float*)d_in[20]; const float* bf1 = (const float*)d_in[21];
    const float* Wf2 = (const float*)d_in[22]; const float* bf2 = (const float*)d_in[23];
    const float* g1  = (const float*)d_in[24]; const float* be1 = (const float*)d_in[25];
    const float* g2  = (const float*)d_in[26]; const float* be2 = (const float*)d_in[27];
    const float* g3  = (const float*)d_in[28]; const float* be3 = (const float*)d_in[29];
    float* out = (float*)d_out;

    float *q, *k, *v, *a, *o, *x1, *x2, *ff;
    cudaGetSymbolAddress((void**)&q,  g_q);
    cudaGetSymbolAddress((void**)&k,  g_k);
    cudaGetSymbolAddress((void**)&v,  g_v);
    cudaGetSymbolAddress((void**)&a,  g_a);
    cudaGetSymbolAddress((void**)&o,  g_o);
    cudaGetSymbolAddress((void**)&x1, g_x1);
    cudaGetSymbolAddress((void**)&x2, g_x2);
    cudaGetSymbolAddress((void**)&ff, g_ff);

    const int FLASH_SMEM = (128 * 65 + 64 * 65 + 64 * 65 + 128 * 65) * 4;  // 99840 B
    cudaFuncSetAttribute(flash_attn, cudaFuncAttributeMaxDynamicSharedMemorySize, FLASH_SMEM);
    const int GEMM_SMEM = 4 * TILE_W * 4;  // 73728 B
    cudaFuncSetAttribute(gemm_tf32, cudaFuncAttributeMaxDynamicSharedMemorySize, GEMM_SMEM);

    const dim3 gProj(DMODEL / 128, ROWS / 128);   // (8, 32)
    const dim3 gFF1 (DFF    / 128, ROWS / 128);   // (32, 32)
    const dim3 gAttn(SEQ / 128, HEADS, BATCH);    // (16, 16, 2)

    // ---- self attention ----
    gemm_tf32<<<gProj, 256, GEMM_SMEM>>>(x, Wq1, bq1, q, ROWS, DMODEL, DMODEL, 0);
    gemm_tf32<<<gProj, 256, GEMM_SMEM>>>(x, Wk1, bk1, k, ROWS, DMODEL, DMODEL, 0);
    gemm_tf32<<<gProj, 256, GEMM_SMEM>>>(x, Wv1, bv1, v, ROWS, DMODEL, DMODEL, 0);
    flash_attn<<<gAttn, 256, FLASH_SMEM>>>(q, k, v, a, SEQ, SEQ, 1);
    gemm_tf32<<<gProj, 256, GEMM_SMEM>>>(a, Wo1, bo1, o, ROWS, DMODEL, DMODEL, 0);
    add_ln<<<ROWS, 256>>>(x, o, g1, be1, x1);

    // ---- cross attention ----
    gemm_tf32<<<gProj, 256, GEMM_SMEM>>>(x1,  Wq2, bq2, q, ROWS, DMODEL, DMODEL, 0);
    gemm_tf32<<<gProj, 256, GEMM_SMEM>>>(enc, Wk2, bk2, k, ROWS, DMODEL, DMODEL, 0);
    gemm_tf32<<<gProj, 256, GEMM_SMEM>>>(enc, Wv2, bv2, v, ROWS, DMODEL, DMODEL, 0);
    flash_attn<<<gAttn, 256, FLASH_SMEM>>>(q, k, v, a, SEQ, SEQ, 0);
    gemm_tf32<<<gProj, 256, GEMM_SMEM>>>(a, Wo2, bo2, o, ROWS, DMODEL, DMODEL, 0);
    add_ln<<<ROWS, 256>>>(x1, o, g2, be2, x2);

    // ---- FFN ----
    gemm_tf32<<<gFF1, 256, GEMM_SMEM>>>(x2, Wf1, bf1, ff, ROWS, DFF, DMODEL, 1);
    gemm_tf32<<<gProj, 256, GEMM_SMEM>>>(ff, Wf2, bf2, o, ROWS, DMODEL, DFF, 0);
    add_ln<<<ROWS, 256>>>(x2, o, g3, be3, out);
}

// round 5
// speedup vs baseline: 3.0431x; 1.6387x over previous
#include <cuda_runtime.h>
#include <math.h>
#include <stdint.h>

// Problem constants
#define BATCH 2
#define SEQ   2048
#define DMODEL 1024
#define HEADS 16
#define DKH   64
#define DFF   4096
#define ROWS  (BATCH * SEQ)   // 4096

// ---------------- scratch (static device globals; no allocation) -------------
__device__ float g_q [ROWS * DMODEL];
__device__ float g_k [ROWS * DMODEL];
__device__ float g_v [ROWS * DMODEL];
__device__ float g_a [ROWS * DMODEL];
__device__ float g_o [ROWS * DMODEL];
__device__ float g_x1[ROWS * DMODEL];
__device__ float g_x2[ROWS * DMODEL];
__device__ float g_ff[(size_t)ROWS * DFF];

__device__ __forceinline__ unsigned smem_u32(const void* p) {
    return (unsigned)__cvta_generic_to_shared(p);
}

// =============================================================================
// TF32 tensor-core GEMM:  C[M,N] = A[M,K] * B[N,K]^T + bias[N]  (optional ReLU)
// 128x128 block tile, K-tile 32, 256 threads (8 warps, 2m x 4n),
// warp tile 64x32 -> 4x4 mma.m16n8k8.tf32. Smem row stride 36 words
// => conflict-free ldmatrix. cp.async double buffering.
// =============================================================================
#define KT     32
#define LDS_S  36                    // padded stride (words) per 32-word row
#define TILE_W (128 * LDS_S)         // words per tile

__global__ __launch_bounds__(256) void gemm_tf32(
    const float* __restrict__ A, const float* __restrict__ B,
    const float* __restrict__ bias, float* __restrict__ C,
    int M, int N, int K, int relu)
{
    extern __shared__ float sh[];
    float* As = sh;                   // 2 stages
    float* Bs = sh + 2 * TILE_W;      // 2 stages

    const int tid  = threadIdx.x;
    const int lane = tid & 31;
    const int w    = tid >> 5;
    const int wm   = w & 1;           // 0..1
    const int wn   = w >> 1;          // 0..3
    const int m0 = blockIdx.y * 128;
    const int n0 = blockIdx.x * 128;

    float acc[4][4][4];
#pragma unroll
    for (int mi = 0; mi < 4; mi++)
#pragma unroll
        for (int ni = 0; ni < 4; ni++)
#pragma unroll
            for (int r = 0; r < 4; r++) acc[mi][ni][r] = 0.f;

    const int lrow0 = tid >> 3;       // row advances by 32 per chunk
    const int lc4   = (tid & 7) << 2; // word offset 0..28 step 4

    auto load_tile = [&](int st, int k0) {
        const float* Asrc = A + (size_t)(m0 + lrow0) * K + k0 + lc4;
        const float* Bsrc = B + (size_t)(n0 + lrow0) * K + k0 + lc4;
        unsigned Adst = smem_u32(As + st * TILE_W + lrow0 * LDS_S + lc4);
        unsigned Bdst = smem_u32(Bs + st * TILE_W + lrow0 * LDS_S + lc4);
#pragma unroll
        for (int i = 0; i < 4; i++) {
            asm volatile("cp.async.cg.shared.global [%0], [%1], 16;\n"
                         :: "r"(Adst + i * 32 * LDS_S * 4),
                            "l"(Asrc + (size_t)i * 32 * K));
            asm volatile("cp.async.cg.shared.global [%0], [%1], 16;\n"
                         :: "r"(Bdst + i * 32 * LDS_S * 4),
                            "l"(Bsrc + (size_t)i * 32 * K));
        }
    };

    const int a_row = wm * 64 + (lane & 7) + ((lane >> 3) & 1) * 8;  // + mi*16
    const int a_cw  = (lane >> 4) * 4;                               // + ks*8
    const int b_row = wn * 32 + (lane & 7) + (lane >> 4) * 8;        // + p*16
    const int b_cw  = ((lane >> 3) & 1) * 4;                         // + ks*8

    load_tile(0, 0);
    asm volatile("cp.async.commit_group;\n");

    const int nk = K >> 5;
    for (int kt = 0; kt < nk; kt++) {
        const int st = kt & 1;
        if (kt + 1 < nk) {
            load_tile((kt + 1) & 1, (kt + 1) << 5);
            asm volatile("cp.async.commit_group;\n");
            asm volatile("cp.async.wait_group 1;\n");
        } else {
            asm volatile("cp.async.wait_group 0;\n");
        }
        __syncthreads();

        const float* Ab = As + st * TILE_W;
        const float* Bb = Bs + st * TILE_W;

#pragma unroll
        for (int ks = 0; ks < 4; ks++) {
            uint32_t af[4][4];
            uint32_t bf[4][2];
#pragma unroll
            for (int mi = 0; mi < 4; mi++) {
                unsigned ad = smem_u32(Ab + (a_row + mi * 16) * LDS_S + ks * 8 + a_cw);
                asm volatile(
                    "ldmatrix.sync.aligned.m8n8.x4.shared.b16 {%0,%1,%2,%3}, [%4];\n"
                    : "=r"(af[mi][0]), "=r"(af[mi][1]), "=r"(af[mi][2]), "=r"(af[mi][3])
                    : "r"(ad));
            }
#pragma unroll
            for (int p = 0; p < 2; p++) {
                unsigned bd = smem_u32(Bb + (b_row + p * 16) * LDS_S + ks * 8 + b_cw);
                asm volatile(
                    "ldmatrix.sync.aligned.m8n8.x4.shared.b16 {%0,%1,%2,%3}, [%4];\n"
                    : "=r"(bf[2 * p][0]), "=r"(bf[2 * p][1]),
                      "=r"(bf[2 * p + 1][0]), "=r"(bf[2 * p + 1][1])
                    : "r"(bd));
            }
#pragma unroll
            for (int mi = 0; mi < 4; mi++)
#pragma unroll
                for (int r = 0; r < 4; r++)
                    asm volatile("cvt.rna.tf32.f32 %0, %0;\n" : "+r"(af[mi][r]));
#pragma unroll
            for (int ni = 0; ni < 4; ni++)
#pragma unroll
                for (int r = 0; r < 2; r++)
                    asm volatile("cvt.rna.tf32.f32 %0, %0;\n" : "+r"(bf[ni][r]));

#pragma unroll
            for (int mi = 0; mi < 4; mi++)
#pragma unroll
                for (int ni = 0; ni < 4; ni++) {
                    asm volatile(
                        "mma.sync.aligned.m16n8k8.row.col.f32.tf32.tf32.f32 "
                        "{%0,%1,%2,%3}, {%4,%5,%6,%7}, {%8,%9}, {%0,%1,%2,%3};\n"
                        : "+f"(acc[mi][ni][0]), "+f"(acc[mi][ni][1]),
                          "+f"(acc[mi][ni][2]), "+f"(acc[mi][ni][3])
                        : "r"(af[mi][0]), "r"(af[mi][1]), "r"(af[mi][2]), "r"(af[mi][3]),
                          "r"(bf[ni][0]), "r"(bf[ni][1]));
                }
        }
        __syncthreads();
    }

#pragma unroll
    for (int mi = 0; mi < 4; mi++) {
        const int row = m0 + wm * 64 + mi * 16 + (lane >> 2);
#pragma unroll
        for (int ni = 0; ni < 4; ni++) {
            const int col = n0 + wn * 32 + ni * 8 + 2 * (lane & 3);
            const float bv0 = bias[col], bv1 = bias[col + 1];
            float v0 = acc[mi][ni][0] + bv0;
            float v1 = acc[mi][ni][1] + bv1;
            float v2 = acc[mi][ni][2] + bv0;
            float v3 = acc[mi][ni][3] + bv1;
            if (relu) {
                v0 = fmaxf(v0, 0.f); v1 = fmaxf(v1, 0.f);
                v2 = fmaxf(v2, 0.f); v3 = fmaxf(v3, 0.f);
            }
            *(float2*)(C + (size_t)row * N + col)       = make_float2(v0, v1);
            *(float2*)(C + (size_t)(row + 8) * N + col) = make_float2(v2, v3);
        }
    }
}

// =============================================================================
// TF32 tensor-core flash attention. Bq=128 (8 warps x 16 rows), Bkv=64, DK=64.
// QK^T and P*V via mma.m16n8k8.tf32; online softmax on register fragments.
// All smem tiles stride 68 words (ldmatrix conflict-free: banks 4r mod 32).
// =============================================================================
#define FST 68                       // flash smem row stride (words)

__global__ __launch_bounds__(256, 2) void flash_attn(
    const float* __restrict__ Qg, const float* __restrict__ Kg,
    const float* __restrict__ Vg, float* __restrict__ Og,
    int qlen, int kvlen, int causal)
{
    extern __shared__ float sm[];
    float* Qs = sm;                  // 128 x 64 (q  x d)
    float* Ks = Qs + 128 * FST;      // 64  x 64 (kv x d)
    float* Vt = Ks + 64 * FST;       // 64  x 64 (d  x kv)  TRANSPOSED
    float* Ps = Vt + 64 * FST;       // 128 x 64 (q  x kv)

    const int tid  = threadIdx.x;
    const int lane = tid & 31;
    const int w    = tid >> 5;
    const int qrow = w * 16;         // warp's base q-row within tile
    const int r0   = lane >> 2;
    const int b  = blockIdx.z;
    const int h  = blockIdx.y;
    const int q0 = blockIdx.x * 128;

    const float* Qb = Qg + (size_t)b * qlen  * DMODEL + h * DKH;
    const float* Kb = Kg + (size_t)b * kvlen * DMODEL + h * DKH;
    const float* Vb = Vg + (size_t)b * kvlen * DMODEL + h * DKH;

    // ldmatrix per-thread mappings (same fragment layout as gemm_tf32)
    const int a_row = qrow + (lane & 7) + ((lane >> 3) & 1) * 8;
    const int a_cw  = (lane >> 4) * 4;
    const int b_rowc = (lane & 7) + (lane >> 4) * 8;   // + p*16
    const int b_cw  = ((lane >> 3) & 1) * 4;

    // load Q tile (pre-scaled by 1/sqrt(64))
    for (int idx = tid; idx < 128 * 16; idx += 256) {
        const int r  = idx >> 4;
        const int c4 = (idx & 15) << 2;
        float4 qv = *(const float4*)(Qb + (size_t)(q0 + r) * DMODEL + c4);
        float* dst = Qs + r * FST + c4;
        dst[0] = qv.x * 0.125f; dst[1] = qv.y * 0.125f;
        dst[2] = qv.z * 0.125f; dst[3] = qv.w * 0.125f;
    }

    float m_i[2], l_i[2], o[8][4];
    m_i[0] = m_i[1] = -1e30f;
    l_i[0] = l_i[1] = 0.f;
#pragma unroll
    for (int ni = 0; ni < 8; ni++)
#pragma unroll
        for (int r = 0; r < 4; r++) o[ni][r] = 0.f;

    const int kv_end = causal ? min(kvlen, q0 + 128) : kvlen;

    for (int kv0 = 0; kv0 < kv_end; kv0 += 64) {
        __syncthreads();  // protect Ks/Vt from previous iteration readers

        // K tile: coalesced copy
        for (int idx = tid; idx < 64 * 16; idx += 256) {
            const int r  = idx >> 4;
            const int c4 = (idx & 15) << 2;
            float4 kv4 = *(const float4*)(Kb + (size_t)(kv0 + r) * DMODEL + c4);
            float* dst = Ks + r * FST + c4;
            dst[0] = kv4.x; dst[1] = kv4.y; dst[2] = kv4.z; dst[3] = kv4.w;
        }
        // V tile: transposed store Vt[d][kv]. lane == kv-row -> 32 distinct banks.
#pragma unroll
        for (int it = 0; it < 4; it++) {
            const int idx = it * 256 + tid;
            const int r  = idx & 63;          // kv row
            const int c4 = (idx >> 6) << 2;   // d offset
            float4 vv4 = *(const float4*)(Vb + (size_t)(kv0 + r) * DMODEL + c4);
            Vt[(c4 + 0) * FST + r] = vv4.x;
            Vt[(c4 + 1) * FST + r] = vv4.y;
            Vt[(c4 + 2) * FST + r] = vv4.z;
            Vt[(c4 + 3) * FST + r] = vv4.w;
        }
        __syncthreads();

        // per-warp skip of fully-masked causal tiles
        if (causal && kv0 > q0 + qrow + 15) continue;

        // ---- S = Q K^T (scaled) ----
        float s[8][4];
#pragma unroll
        for (int ni = 0; ni < 8; ni++)
#pragma unroll
            for (int r = 0; r < 4; r++) s[ni][r] = 0.f;

#pragma unroll
        for (int ks = 0; ks < 8; ks++) {
            uint32_t af[4], bf[8][2];
            unsigned ad = smem_u32(Qs + a_row * FST + ks * 8 + a_cw);
            asm volatile(
                "ldmatrix.sync.aligned.m8n8.x4.shared.b16 {%0,%1,%2,%3}, [%4];\n"
                : "=r"(af[0]), "=r"(af[1]), "=r"(af[2]), "=r"(af[3]) : "r"(ad));
#pragma unroll
            for (int p = 0; p < 4; p++) {
                unsigned bd = smem_u32(Ks + (p * 16 + b_rowc) * FST + ks * 8 + b_cw);
                asm volatile(
                    "ldmatrix.sync.aligned.m8n8.x4.shared.b16 {%0,%1,%2,%3}, [%4];\n"
                    : "=r"(bf[2 * p][0]), "=r"(bf[2 * p][1]),
                      "=r"(bf[2 * p + 1][0]), "=r"(bf[2 * p + 1][1])
                    : "r"(bd));
            }
#pragma unroll
            for (int r = 0; r < 4; r++)
                asm volatile("cvt.rna.tf32.f32 %0, %0;\n" : "+r"(af[r]));
#pragma unroll
            for (int ni = 0; ni < 8; ni++)
#pragma unroll
                for (int r = 0; r < 2; r++)
                    asm volatile("cvt.rna.tf32.f32 %0, %0;\n" : "+r"(bf[ni][r]));
#pragma unroll
            for (int ni = 0; ni < 8; ni++) {
                asm volatile(
                    "mma.sync.aligned.m16n8k8.row.col.f32.tf32.tf32.f32 "
                    "{%0,%1,%2,%3}, {%4,%5,%6,%7}, {%8,%9}, {%0,%1,%2,%3};\n"
                    : "+f"(s[ni][0]), "+f"(s[ni][1]), "+f"(s[ni][2]), "+f"(s[ni][3])
                    : "r"(af[0]), "r"(af[1]), "r"(af[2]), "r"(af[3]),
                      "r"(bf[ni][0]), "r"(bf[ni][1]));
            }
        }

        // ---- causal mask ----
        if (causal && kv0 + 63 > q0 + qrow) {
            const int row0 = q0 + qrow + r0;
            const int colb = kv0 + 2 * (lane & 3);
#pragma unroll
            for (int ni = 0; ni < 8; ni++) {
                const int c = colb + ni * 8;
                if (c     > row0    ) s[ni][0] = -1e30f;
                if (c + 1 > row0    ) s[ni][1] = -1e30f;
                if (c     > row0 + 8) s[ni][2] = -1e30f;
                if (c + 1 > row0 + 8) s[ni][3] = -1e30f;
            }
        }

        // ---- online softmax (rows r0 and r0+8); P -> smem ----
#pragma unroll
        for (int hh = 0; hh < 2; hh++) {
            float mt = -1e30f;
#pragma unroll
            for (int ni = 0; ni < 8; ni++)
                mt = fmaxf(mt, fmaxf(s[ni][2 * hh], s[ni][2 * hh + 1]));
            mt = fmaxf(mt, __shfl_xor_sync(0xffffffffu, mt, 1));
            mt = fmaxf(mt, __shfl_xor_sync(0xffffffffu, mt, 2));
            const float mn = fmaxf(m_i[hh], mt);
            const float corr = __expf(m_i[hh] - mn);
            m_i[hh] = mn;
            float rs = 0.f;
            float* Prow = Ps + (qrow + r0 + 8 * hh) * FST + 2 * (lane & 3);
#pragma unroll
            for (int ni = 0; ni < 8; ni++) {
                const float p0 = __expf(s[ni][2 * hh]     - mn);
                const float p1 = __expf(s[ni][2 * hh + 1] - mn);
                rs += p0 + p1;
                *(float2*)(Prow + ni * 8) = make_float2(p0, p1);
            }
            rs += __shfl_xor_sync(0xffffffffu, rs, 1);
            rs += __shfl_xor_sync(0xffffffffu, rs, 2);
            l_i[hh] = l_i[hh] * corr + rs;
#pragma unroll
            for (int ni = 0; ni < 8; ni++) {
                o[ni][2 * hh]     *= corr;
                o[ni][2 * hh + 1] *= corr;
            }
        }
        __syncwarp();  // P rows are warp-private: warp-level visibility suffices

        // ---- O += P * V ----
#pragma unroll
        for (int ks = 0; ks < 8; ks++) {
            uint32_t af[4], bf[8][2];
            unsigned ad = smem_u32(Ps + a_row * FST + ks * 8 + a_cw);
            asm volatile(
                "ldmatrix.sync.aligned.m8n8.x4.shared.b16 {%0,%1,%2,%3}, [%4];\n"
                : "=r"(af[0]), "=r"(af[1]), "=r"(af[2]), "=r"(af[3]) : "r"(ad));
#pragma unroll
            for (int p = 0; p < 4; p++) {
                unsigned bd = smem_u32(Vt + (p * 16 + b_rowc) * FST + ks * 8 + b_cw);
                asm volatile(
                    "ldmatrix.sync.aligned.m8n8.x4.shared.b16 {%0,%1,%2,%3}, [%4];\n"
                    : "=r"(bf[2 * p][0]), "=r"(bf[2 * p][1]),
                      "=r"(bf[2 * p + 1][0]), "=r"(bf[2 * p + 1][1])
                    : "r"(bd));
            }
#pragma unroll
            for (int r = 0; r < 4; r++)
                asm volatile("cvt.rna.tf32.f32 %0, %0;\n" : "+r"(af[r]));
#pragma unroll
            for (int ni = 0; ni < 8; ni++)
#pragma unroll
                for (int r = 0; r < 2; r++)
                    asm volatile("cvt.rna.tf32.f32 %0, %0;\n" : "+r"(bf[ni][r]));
#pragma unroll
            for (int ni = 0; ni < 8; ni++) {
                asm volatile(
                    "mma.sync.aligned.m16n8k8.row.col.f32.tf32.tf32.f32 "
                    "{%0,%1,%2,%3}, {%4,%5,%6,%7}, {%8,%9}, {%0,%1,%2,%3};\n"
                    : "+f"(o[ni][0]), "+f"(o[ni][1]), "+f"(o[ni][2]), "+f"(o[ni][3])
                    : "r"(af[0]), "r"(af[1]), "r"(af[2]), "r"(af[3]),
                      "r"(bf[ni][0]), "r"(bf[ni][1]));
            }
        }
    }

    // ---- normalize + write ----
    const float inv0 = 1.f / l_i[0];
    const float inv1 = 1.f / l_i[1];
    const int row0 = q0 + qrow + r0;
    float* O0 = Og + ((size_t)b * qlen + row0) * DMODEL + h * DKH + 2 * (lane & 3);
    float* O1 = O0 + (size_t)8 * DMODEL;
#pragma unroll
    for (int ni = 0; ni < 8; ni++) {
        *(float2*)(O0 + ni * 8) = make_float2(o[ni][0] * inv0, o[ni][1] * inv0);
        *(float2*)(O1 + ni * 8) = make_float2(o[ni][2] * inv1, o[ni][3] * inv1);
    }
}

// =============================================================================
// out = LayerNorm(x + y) * g + be      (one block per row of 1024)
// =============================================================================
__global__ __launch_bounds__(256) void add_ln(
    const float* __restrict__ X, const float* __restrict__ Y,
    const float* __restrict__ g, const float* __restrict__ be,
    float* __restrict__ Out)
{
    __shared__ float red[8];
    const int row = blockIdx.x;
    const int tid = threadIdx.x;
    const float* xr = X + (size_t)row * DMODEL;
    const float* yr = Y + (size_t)row * DMODEL;

    float v[4];
    float s = 0.f;
#pragma unroll
    for (int c = 0; c < 4; c++) {
        const int idx = tid + 256 * c;
        v[c] = xr[idx] + yr[idx];
        s += v[c];
    }
#pragma unroll
    for (int off = 16; off >= 1; off >>= 1) s += __shfl_xor_sync(0xffffffffu, s, off);
    if ((tid & 31) == 0) red[tid >> 5] = s;
    __syncthreads();
    if (tid < 32) {
        float t = (tid < 8) ? red[tid] : 0.f;
#pragma unroll
        for (int off = 4; off >= 1; off >>= 1) t += __shfl_xor_sync(0xffffffffu, t, off);
        if (tid == 0) red[0] = t;
    }
    __syncthreads();
    const float mu = red[0] * (1.f / DMODEL);
    __syncthreads();

    float sq = 0.f;
#pragma unroll
    for (int c = 0; c < 4; c++) {
        const float d = v[c] - mu;
        sq += d * d;
    }
#pragma unroll
    for (int off = 16; off >= 1; off >>= 1) sq += __shfl_xor_sync(0xffffffffu, sq, off);
    if ((tid & 31) == 0) red[tid >> 5] = sq;
    __syncthreads();
    if (tid < 32) {
        float t = (tid < 8) ? red[tid] : 0.f;
#pragma unroll
        for (int off = 4; off >= 1; off >>= 1) t += __shfl_xor_sync(0xffffffffu, t, off);
        if (tid == 0) red[0] = t;
    }
    __syncthreads();
    const float rstd = rsqrtf(red[0] * (1.f / DMODEL) + 1e-5f);

    float* orow = Out + (size_t)row * DMODEL;
#pragma unroll
    for (int c = 0; c < 4; c++) {
        const int idx = tid + 256 * c;
        orow[idx] = (v[c] - mu) * rstd * g[idx] + be[idx];
    }
}

// =============================================================================
// Launch
// =============================================================================
extern "C" void kernel_launch(void* const* d_in, const int* in_sizes, int n_in,
                              void* d_out, int out_size)
{
    (void)in_sizes; (void)n_in; (void)out_size;
    const float* x     = (const float*)d_in[0];
    const float* enc   = (const float*)d_in[1];
    const float* Wq1 = (const float*)d_in[4];  const float* bq1 = (const float*)d_in[5];
    const float* Wk1 = (const float*)d_in[6];  const float* bk1 = (const float*)d_in[7];
    const float* Wv1 = (const float*)d_in[8];  const float* bv1 = (const float*)d_in[9];
    const float* Wo1 = (const float*)d_in[10]; const float* bo1 = (const float*)d_in[11];
    const float* Wq2 = (const float*)d_in[12]; const float* bq2 = (const float*)d_in[13];
    const float* Wk2 = (const float*)d_in[14]; const float* bk2 = (const float*)d_in[15];
    const float* Wv2 = (const float*)d_in[16]; const float* bv2 = (const float*)d_in[17];
    const float* Wo2 = (const float*)d_in[18]; const float* bo2 = (const float*)d_in[19];
    const float* Wf1 = (const float*)d_in[20]; const float* bf1 = (const float*)d_in[21];
    const float* Wf2 = (const float*)d_in[22]; const float* bf2 = (const float*)d_in[23];
    const float* g1  = (const float*)d_in[24]; const float* be1 = (const float*)d_in[25];
    const float* g2  = (const float*)d_in[26]; const float* be2 = (const float*)d_in[27];
    const float* g3  = (const float*)d_in[28]; const float* be3 = (const float*)d_in[29];
    float* out = (float*)d_out;

    float *q, *k, *v, *a, *o, *x1, *x2, *ff;
    cudaGetSymbolAddress((void**)&q,  g_q);
    cudaGetSymbolAddress((void**)&k,  g_k);
    cudaGetSymbolAddress((void**)&v,  g_v);
    cudaGetSymbolAddress((void**)&a,  g_a);
    cudaGetSymbolAddress((void**)&o,  g_o);
    cudaGetSymbolAddress((void**)&x1, g_x1);
    cudaGetSymbolAddress((void**)&x2, g_x2);
    cudaGetSymbolAddress((void**)&ff, g_ff);

    const int FLASH_SMEM = (128 + 64 + 64 + 128) * FST * 4;  // 104448 B
    cudaFuncSetAttribute(flash_attn, cudaFuncAttributeMaxDynamicSharedMemorySize, FLASH_SMEM);
    const int GEMM_SMEM = 4 * TILE_W * 4;  // 73728 B
    cudaFuncSetAttribute(gemm_tf32, cudaFuncAttributeMaxDynamicSharedMemorySize, GEMM_SMEM);

    const dim3 gProj(DMODEL / 128, ROWS / 128);   // (8, 32)
    const dim3 gFF1 (DFF    / 128, ROWS / 128);   // (32, 32)
    const dim3 gAttn(SEQ / 128, HEADS, BATCH);    // (16, 16, 2)

    // ---- self attention ----
    gemm_tf32<<<gProj, 256, GEMM_SMEM>>>(x, Wq1, bq1, q, ROWS, DMODEL, DMODEL, 0);
    gemm_tf32<<<gProj, 256, GEMM_SMEM>>>(x, Wk1, bk1, k, ROWS, DMODEL, DMODEL, 0);
    gemm_tf32<<<gProj, 256, GEMM_SMEM>>>(x, Wv1, bv1, v, ROWS, DMODEL, DMODEL, 0);
    flash_attn<<<gAttn, 256, FLASH_SMEM>>>(q, k, v, a, SEQ, SEQ, 1);
    gemm_tf32<<<gProj, 256, GEMM_SMEM>>>(a, Wo1, bo1, o, ROWS, DMODEL, DMODEL, 0);
    add_ln<<<ROWS, 256>>>(x, o, g1, be1, x1);

    // ---- cross attention ----
    gemm_tf32<<<gProj, 256, GEMM_SMEM>>>(x1,  Wq2, bq2, q, ROWS, DMODEL, DMODEL, 0);
    gemm_tf32<<<gProj, 256, GEMM_SMEM>>>(enc, Wk2, bk2, k, ROWS, DMODEL, DMODEL, 0);
    gemm_tf32<<<gProj, 256, GEMM_SMEM>>>(enc, Wv2, bv2, v, ROWS, DMODEL, DMODEL, 0);
    flash_attn<<<gAttn, 256, FLASH_SMEM>>>(q, k, v, a, SEQ, SEQ, 0);
    gemm_tf32<<<gProj, 256, GEMM_SMEM>>>(a, Wo2, bo2, o, ROWS, DMODEL, DMODEL, 0);
    add_ln<<<ROWS, 256>>>(x1, o, g2, be2, x2);

    // ---- FFN ----
    gemm_tf32<<<gFF1, 256, GEMM_SMEM>>>(x2, Wf1, bf1, ff, ROWS, DFF, DMODEL, 1);
    gemm_tf32<<<gProj, 256, GEMM_SMEM>>>(ff, Wf2, bf2, o, ROWS, DMODEL, DFF, 0);
    add_ln<<<ROWS, 256>>>(x2, o, g3, be3, out);
}

// round 6
// speedup vs baseline: 5.4824x; 1.8015x over previous
#include <cuda_runtime.h>
#include <cuda_fp16.h>
#include <math.h>
#include <stdint.h>

// Problem constants
#define BATCH 2
#define SEQ   2048
#define DMODEL 1024
#define HEADS 16
#define DKH   64
#define DFF   4096
#define ROWS  (BATCH * SEQ)   // 4096

// ---------------- scratch (static device globals; no allocation) -------------
__device__ float  g_o  [ROWS * DMODEL];
__device__ float  g_x1 [ROWS * DMODEL];
__device__ float  g_x2 [ROWS * DMODEL];

__device__ __half g_xh  [ROWS * DMODEL];
__device__ __half g_ench[ROWS * DMODEL];
__device__ __half g_qh  [ROWS * DMODEL];
__device__ __half g_kh  [ROWS * DMODEL];
__device__ __half g_vh  [ROWS * DMODEL];
__device__ __half g_ah  [ROWS * DMODEL];
__device__ __half g_x1h [ROWS * DMODEL];
__device__ __half g_x2h [ROWS * DMODEL];
__device__ __half g_ffh [(size_t)ROWS * DFF];
__device__ __half g_wq1h[DMODEL * DMODEL];
__device__ __half g_wk1h[DMODEL * DMODEL];
__device__ __half g_wv1h[DMODEL * DMODEL];
__device__ __half g_wo1h[DMODEL * DMODEL];
__device__ __half g_wq2h[DMODEL * DMODEL];
__device__ __half g_wk2h[DMODEL * DMODEL];
__device__ __half g_wv2h[DMODEL * DMODEL];
__device__ __half g_wo2h[DMODEL * DMODEL];
__device__ __half g_wf1h[DFF * DMODEL];
__device__ __half g_wf2h[DMODEL * DFF];

__device__ __forceinline__ unsigned smem_u32(const void* p) {
    return (unsigned)__cvta_generic_to_shared(p);
}

// =============================================================================
// Batched f32 -> f16 conversion (weights + x + enc) in one launch
// =============================================================================
#define N_CONV 12
struct ConvEnt { const float* s; __half* d; int n; };
struct ConvTab { ConvEnt e[N_CONV]; };

__global__ __launch_bounds__(256) void conv_many(ConvTab t) {
    ConvEnt ent = t.e[blockIdx.y];
    const int i = (blockIdx.x * 256 + threadIdx.x) * 4;
    if (i >= ent.n) return;
    float4 f = *(const float4*)(ent.s + i);
    *(__half2*)(ent.d + i)     = __floats2half2_rn(f.x, f.y);
    *(__half2*)(ent.d + i + 2) = __floats2half2_rn(f.z, f.w);
}

// =============================================================================
// FP16 tensor-core GEMM:  C[M,N] = A[M,K] * B[N,K]^T + bias[N]
// 128x128 tile, K-tile 32, 256 threads (8 warps 2m x 4n), warp tile 64x32,
// mma.m16n8k16.f32.f16.f16.f32. Smem row stride 40 halves (conflict-free
// ldmatrix: 4-word segments at banks 4r*? tile all 32). 3-stage cp.async.
// Epilogue: optional ReLU; writes fp32 (C32) and/or fp16*scale (C16).
// =============================================================================
#define GLD 40                       // halves per smem row (32 data + 8 pad)
#define GTILE (128 * GLD)            // halves per stage per matrix

__global__ __launch_bounds__(256, 2) void gemm_f16(
    const __half* __restrict__ A, const __half* __restrict__ B,
    const float* __restrict__ bias, float* __restrict__ C32,
    __half* __restrict__ C16,
    int M, int N, int K, int relu, float scale)
{
    extern __shared__ __half shh[];
    __half* As = shh;                 // 3 stages
    __half* Bs = shh + 3 * GTILE;     // 3 stages

    const int tid  = threadIdx.x;
    const int lane = tid & 31;
    const int w    = tid >> 5;
    const int wm   = w & 1;
    const int wn   = w >> 1;
    const int m0 = blockIdx.y * 128;
    const int n0 = blockIdx.x * 128;

    float acc[4][4][4];
#pragma unroll
    for (int mi = 0; mi < 4; mi++)
#pragma unroll
        for (int ni = 0; ni < 4; ni++)
#pragma unroll
            for (int r = 0; r < 4; r++) acc[mi][ni][r] = 0.f;

    // loader: 512 16B-chunks per matrix per stage; 2 per thread per matrix
    auto load_tile = [&](int st, int k0) {
#pragma unroll
        for (int i = 0; i < 2; i++) {
            const int idx = tid + i * 256;
            const int row = idx >> 2;
            const int c   = (idx & 3) * 8;
            unsigned Adst = smem_u32(As + st * GTILE + row * GLD + c);
            unsigned Bdst = smem_u32(Bs + st * GTILE + row * GLD + c);
            asm volatile("cp.async.cg.shared.global [%0], [%1], 16;\n"
                         :: "r"(Adst), "l"(A + (size_t)row * K + k0 + c));
            asm volatile("cp.async.cg.shared.global [%0], [%1], 16;\n"
                         :: "r"(Bdst), "l"(B + (size_t)row * K + k0 + c));
        }
    };
    // shift A/B base by block offsets once
    A += (size_t)m0 * K;
    B += (size_t)n0 * K;

    const int a_row  = wm * 64 + (lane & 15);   // + mi*16
    const int b_row  = wn * 32 + (lane & 15);   // + pj*16
    const int colh   = (lane >> 4) * 8;         // + ks*16

    load_tile(0, 0);
    asm volatile("cp.async.commit_group;\n");
    load_tile(1, 32);
    asm volatile("cp.async.commit_group;\n");

    const int nk = K >> 5;
    for (int kt = 0; kt < nk; kt++) {
        asm volatile("cp.async.wait_group 1;\n");
        __syncthreads();

        if (kt + 2 < nk) load_tile((kt + 2) % 3, (kt + 2) << 5);
        asm volatile("cp.async.commit_group;\n");

        const __half* Ab = As + (kt % 3) * GTILE;
        const __half* Bb = Bs + (kt % 3) * GTILE;

#pragma unroll
        for (int ks = 0; ks < 2; ks++) {
            uint32_t af[4][4], bf[4][2];
#pragma unroll
            for (int mi = 0; mi < 4; mi++) {
                unsigned ad = smem_u32(Ab + (a_row + mi * 16) * GLD + ks * 16 + colh);
                asm volatile(
                    "ldmatrix.sync.aligned.m8n8.x4.shared.b16 {%0,%1,%2,%3}, [%4];\n"
                    : "=r"(af[mi][0]), "=r"(af[mi][1]), "=r"(af[mi][2]), "=r"(af[mi][3])
                    : "r"(ad));
            }
#pragma unroll
            for (int pj = 0; pj < 2; pj++) {
                uint32_t r0, r1, r2, r3;
                unsigned bd = smem_u32(Bb + (b_row + pj * 16) * GLD + ks * 16 + colh);
                asm volatile(
                    "ldmatrix.sync.aligned.m8n8.x4.shared.b16 {%0,%1,%2,%3}, [%4];\n"
                    : "=r"(r0), "=r"(r1), "=r"(r2), "=r"(r3) : "r"(bd));
                bf[2 * pj][0] = r0; bf[2 * pj][1] = r2;
                bf[2 * pj + 1][0] = r1; bf[2 * pj + 1][1] = r3;
            }
#pragma unroll
            for (int mi = 0; mi < 4; mi++)
#pragma unroll
                for (int ni = 0; ni < 4; ni++) {
                    asm volatile(
                        "mma.sync.aligned.m16n8k16.row.col.f32.f16.f16.f32 "
                        "{%0,%1,%2,%3}, {%4,%5,%6,%7}, {%8,%9}, {%0,%1,%2,%3};\n"
                        : "+f"(acc[mi][ni][0]), "+f"(acc[mi][ni][1]),
                          "+f"(acc[mi][ni][2]), "+f"(acc[mi][ni][3])
                        : "r"(af[mi][0]), "r"(af[mi][1]), "r"(af[mi][2]), "r"(af[mi][3]),
                          "r"(bf[ni][0]), "r"(bf[ni][1]));
                }
        }
        __syncthreads();
    }

#pragma unroll
    for (int mi = 0; mi < 4; mi++) {
        const int row = m0 + wm * 64 + mi * 16 + (lane >> 2);
#pragma unroll
        for (int ni = 0; ni < 4; ni++) {
            const int col = n0 + wn * 32 + ni * 8 + 2 * (lane & 3);
            const float bv0 = bias[col], bv1 = bias[col + 1];
            float v0 = acc[mi][ni][0] + bv0;
            float v1 = acc[mi][ni][1] + bv1;
            float v2 = acc[mi][ni][2] + bv0;
            float v3 = acc[mi][ni][3] + bv1;
            if (relu) {
                v0 = fmaxf(v0, 0.f); v1 = fmaxf(v1, 0.f);
                v2 = fmaxf(v2, 0.f); v3 = fmaxf(v3, 0.f);
            }
            if (C32) {
                *(float2*)(C32 + (size_t)row * N + col)       = make_float2(v0, v1);
                *(float2*)(C32 + (size_t)(row + 8) * N + col) = make_float2(v2, v3);
            }
            if (C16) {
                *(__half2*)(C16 + (size_t)row * N + col) =
                    __floats2half2_rn(v0 * scale, v1 * scale);
                *(__half2*)(C16 + (size_t)(row + 8) * N + col) =
                    __floats2half2_rn(v2 * scale, v3 * scale);
            }
        }
    }
}

// =============================================================================
// FP16 tensor-core flash attention. Bq=128 (8 warps x 16 rows), Bkv=64, DK=64.
// Q pre-scaled by 1/8 at production. Smem stride 72 halves (conflict-free).
// =============================================================================
#define FSH 72

__global__ __launch_bounds__(256, 2) void flash_attn(
    const __half* __restrict__ Qg, const __half* __restrict__ Kg,
    const __half* __restrict__ Vg, __half* __restrict__ Og,
    int qlen, int kvlen, int causal)
{
    extern __shared__ __half smh[];
    __half* Qs = smh;                 // 128 x 64 (q  x d)
    __half* Ks = Qs + 128 * FSH;      // 64  x 64 (kv x d)
    __half* Vt = Ks + 64 * FSH;       // 64  x 64 (d  x kv)  transposed
    __half* Ps = Vt + 64 * FSH;       // 128 x 64 (q  x kv)

    const int tid  = threadIdx.x;
    const int lane = tid & 31;
    const int w    = tid >> 5;
    const int qrow = w * 16;
    const int r0   = lane >> 2;
    const int b  = blockIdx.z;
    const int h  = blockIdx.y;
    const int q0 = blockIdx.x * 128;

    const __half* Qb = Qg + (size_t)b * qlen  * DMODEL + h * DKH;
    const __half* Kb = Kg + (size_t)b * kvlen * DMODEL + h * DKH;
    const __half* Vb = Vg + (size_t)b * kvlen * DMODEL + h * DKH;

    const int a_row = qrow + (lane & 15);
    const int colh  = (lane >> 4) * 8;
    const int b_rowc = lane & 15;

    // Q tile: 1024 16B chunks, 4 per thread
#pragma unroll
    for (int it = 0; it < 4; it++) {
        const int idx = tid + it * 256;
        const int r = idx >> 3;
        const int c = (idx & 7) * 8;
        *(uint4*)(Qs + r * FSH + c) = *(const uint4*)(Qb + (size_t)(q0 + r) * DMODEL + c);
    }

    float m_i[2], l_i[2], o[8][4];
    m_i[0] = m_i[1] = -1e30f;
    l_i[0] = l_i[1] = 0.f;
#pragma unroll
    for (int ni = 0; ni < 8; ni++)
#pragma unroll
        for (int r = 0; r < 4; r++) o[ni][r] = 0.f;

    const int kv_end = causal ? min(kvlen, q0 + 128) : kvlen;

    for (int kv0 = 0; kv0 < kv_end; kv0 += 64) {
        __syncthreads();
        // K tile: 512 chunks, 2 per thread
#pragma unroll
        for (int it = 0; it < 2; it++) {
            const int idx = tid + it * 256;
            const int r = idx >> 3;
            const int c = (idx & 7) * 8;
            *(uint4*)(Ks + r * FSH + c) = *(const uint4*)(Kb + (size_t)(kv0 + r) * DMODEL + c);
        }
        // V tile transposed: 512 items, 2 per thread
#pragma unroll
        for (int it = 0; it < 2; it++) {
            const int idx = tid + it * 256;
            const int r  = idx & 63;
            const int c8 = (idx >> 6) * 8;
            uint4 raw = *(const uint4*)(Vb + (size_t)(kv0 + r) * DMODEL + c8);
            const __half* hv = (const __half*)&raw;
#pragma unroll
            for (int i = 0; i < 8; i++) Vt[(c8 + i) * FSH + r] = hv[i];
        }
        __syncthreads();

        if (causal && kv0 > q0 + qrow + 15) continue;

        // ---- S = Q K^T ----
        float s[8][4];
#pragma unroll
        for (int ni = 0; ni < 8; ni++)
#pragma unroll
            for (int r = 0; r < 4; r++) s[ni][r] = 0.f;

#pragma unroll
        for (int ks = 0; ks < 4; ks++) {
            uint32_t af[4], bf[8][2];
            unsigned ad = smem_u32(Qs + a_row * FSH + ks * 16 + colh);
            asm volatile(
                "ldmatrix.sync.aligned.m8n8.x4.shared.b16 {%0,%1,%2,%3}, [%4];\n"
                : "=r"(af[0]), "=r"(af[1]), "=r"(af[2]), "=r"(af[3]) : "r"(ad));
#pragma unroll
            for (int pj = 0; pj < 4; pj++) {
                uint32_t r0r, r1r, r2r, r3r;
                unsigned bd = smem_u32(Ks + (pj * 16 + b_rowc) * FSH + ks * 16 + colh);
                asm volatile(
                    "ldmatrix.sync.aligned.m8n8.x4.shared.b16 {%0,%1,%2,%3}, [%4];\n"
                    : "=r"(r0r), "=r"(r1r), "=r"(r2r), "=r"(r3r) : "r"(bd));
                bf[2 * pj][0] = r0r; bf[2 * pj][1] = r2r;
                bf[2 * pj + 1][0] = r1r; bf[2 * pj + 1][1] = r3r;
            }
#pragma unroll
            for (int ni = 0; ni < 8; ni++) {
                asm volatile(
                    "mma.sync.aligned.m16n8k16.row.col.f32.f16.f16.f32 "
                    "{%0,%1,%2,%3}, {%4,%5,%6,%7}, {%8,%9}, {%0,%1,%2,%3};\n"
                    : "+f"(s[ni][0]), "+f"(s[ni][1]), "+f"(s[ni][2]), "+f"(s[ni][3])
                    : "r"(af[0]), "r"(af[1]), "r"(af[2]), "r"(af[3]),
                      "r"(bf[ni][0]), "r"(bf[ni][1]));
            }
        }

        // ---- causal mask ----
        if (causal && kv0 + 63 > q0 + qrow) {
            const int row0 = q0 + qrow + r0;
            const int colb = kv0 + 2 * (lane & 3);
#pragma unroll
            for (int ni = 0; ni < 8; ni++) {
                const int c = colb + ni * 8;
                if (c     > row0    ) s[ni][0] = -1e30f;
                if (c + 1 > row0    ) s[ni][1] = -1e30f;
                if (c     > row0 + 8) s[ni][2] = -1e30f;
                if (c + 1 > row0 + 8) s[ni][3] = -1e30f;
            }
        }

        // ---- online softmax; P -> smem (fp16) ----
#pragma unroll
        for (int hh = 0; hh < 2; hh++) {
            float mt = -1e30f;
#pragma unroll
            for (int ni = 0; ni < 8; ni++)
                mt = fmaxf(mt, fmaxf(s[ni][2 * hh], s[ni][2 * hh + 1]));
            mt = fmaxf(mt, __shfl_xor_sync(0xffffffffu, mt, 1));
            mt = fmaxf(mt, __shfl_xor_sync(0xffffffffu, mt, 2));
            const float mn = fmaxf(m_i[hh], mt);
            const float corr = __expf(m_i[hh] - mn);
            m_i[hh] = mn;
            float rs = 0.f;
            __half* Prow = Ps + (qrow + r0 + 8 * hh) * FSH + 2 * (lane & 3);
#pragma unroll
            for (int ni = 0; ni < 8; ni++) {
                const float p0 = __expf(s[ni][2 * hh]     - mn);
                const float p1 = __expf(s[ni][2 * hh + 1] - mn);
                rs += p0 + p1;
                *(__half2*)(Prow + ni * 8) = __floats2half2_rn(p0, p1);
            }
            rs += __shfl_xor_sync(0xffffffffu, rs, 1);
            rs += __shfl_xor_sync(0xffffffffu, rs, 2);
            l_i[hh] = l_i[hh] * corr + rs;
#pragma unroll
            for (int ni = 0; ni < 8; ni++) {
                o[ni][2 * hh]     *= corr;
                o[ni][2 * hh + 1] *= corr;
            }
        }
        __syncwarp();  // P rows are warp-private

        // ---- O += P * V ----
#pragma unroll
        for (int ks = 0; ks < 4; ks++) {
            uint32_t af[4], bf[8][2];
            unsigned ad = smem_u32(Ps + a_row * FSH + ks * 16 + colh);
            asm volatile(
                "ldmatrix.sync.aligned.m8n8.x4.shared.b16 {%0,%1,%2,%3}, [%4];\n"
                : "=r"(af[0]), "=r"(af[1]), "=r"(af[2]), "=r"(af[3]) : "r"(ad));
#pragma unroll
            for (int pj = 0; pj < 4; pj++) {
                uint32_t r0r, r1r, r2r, r3r;
                unsigned bd = smem_u32(Vt + (pj * 16 + b_rowc) * FSH + ks * 16 + colh);
                asm volatile(
                    "ldmatrix.sync.aligned.m8n8.x4.shared.b16 {%0,%1,%2,%3}, [%4];\n"
                    : "=r"(r0r), "=r"(r1r), "=r"(r2r), "=r"(r3r) : "r"(bd));
                bf[2 * pj][0] = r0r; bf[2 * pj][1] = r2r;
                bf[2 * pj + 1][0] = r1r; bf[2 * pj + 1][1] = r3r;
            }
#pragma unroll
            for (int ni = 0; ni < 8; ni++) {
                asm volatile(
                    "mma.sync.aligned.m16n8k16.row.col.f32.f16.f16.f32 "
                    "{%0,%1,%2,%3}, {%4,%5,%6,%7}, {%8,%9}, {%0,%1,%2,%3};\n"
                    : "+f"(o[ni][0]), "+f"(o[ni][1]), "+f"(o[ni][2]), "+f"(o[ni][3])
                    : "r"(af[0]), "r"(af[1]), "r"(af[2]), "r"(af[3]),
                      "r"(bf[ni][0]), "r"(bf[ni][1]));
            }
        }
    }

    // ---- normalize + write (fp16) ----
    const float inv0 = 1.f / l_i[0];
    const float inv1 = 1.f / l_i[1];
    const int row0 = q0 + qrow + r0;
    __half* O0 = Og + ((size_t)b * qlen + row0) * DMODEL + h * DKH + 2 * (lane & 3);
    __half* O1 = O0 + (size_t)8 * DMODEL;
#pragma unroll
    for (int ni = 0; ni < 8; ni++) {
        *(__half2*)(O0 + ni * 8) = __floats2half2_rn(o[ni][0] * inv0, o[ni][1] * inv0);
        *(__half2*)(O1 + ni * 8) = __floats2half2_rn(o[ni][2] * inv1, o[ni][3] * inv1);
    }
}

// =============================================================================
// out = LayerNorm(x + y) * g + be ; optional fp16 copy
// =============================================================================
__global__ __launch_bounds__(256) void add_ln(
    const float* __restrict__ X, const float* __restrict__ Y,
    const float* __restrict__ g, const float* __restrict__ be,
    float* __restrict__ Out, __half* __restrict__ Out16)
{
    __shared__ float red[8];
    const int row = blockIdx.x;
    const int tid = threadIdx.x;
    const float* xr = X + (size_t)row * DMODEL;
    const float* yr = Y + (size_t)row * DMODEL;

    float v[4];
    float s = 0.f;
#pragma unroll
    for (int c = 0; c < 4; c++) {
        const int idx = tid + 256 * c;
        v[c] = xr[idx] + yr[idx];
        s += v[c];
    }
#pragma unroll
    for (int off = 16; off >= 1; off >>= 1) s += __shfl_xor_sync(0xffffffffu, s, off);
    if ((tid & 31) == 0) red[tid >> 5] = s;
    __syncthreads();
    if (tid < 32) {
        float t = (tid < 8) ? red[tid] : 0.f;
#pragma unroll
        for (int off = 4; off >= 1; off >>= 1) t += __shfl_xor_sync(0xffffffffu, t, off);
        if (tid == 0) red[0] = t;
    }
    __syncthreads();
    const float mu = red[0] * (1.f / DMODEL);
    __syncthreads();

    float sq = 0.f;
#pragma unroll
    for (int c = 0; c < 4; c++) {
        const float d = v[c] - mu;
        sq += d * d;
    }
#pragma unroll
    for (int off = 16; off >= 1; off >>= 1) sq += __shfl_xor_sync(0xffffffffu, sq, off);
    if ((tid & 31) == 0) red[tid >> 5] = sq;
    __syncthreads();
    if (tid < 32) {
        float t = (tid < 8) ? red[tid] : 0.f;
#pragma unroll
        for (int off = 4; off >= 1; off >>= 1) t += __shfl_xor_sync(0xffffffffu, t, off);
        if (tid == 0) red[0] = t;
    }
    __syncthreads();
    const float rstd = rsqrtf(red[0] * (1.f / DMODEL) + 1e-5f);

    float* orow = Out + (size_t)row * DMODEL;
#pragma unroll
    for (int c = 0; c < 4; c++) {
        const int idx = tid + 256 * c;
        const float val = (v[c] - mu) * rstd * g[idx] + be[idx];
        orow[idx] = val;
        if (Out16) Out16[(size_t)row * DMODEL + idx] = __float2half(val);
    }
}

// =============================================================================
// Launch
// =============================================================================
extern "C" void kernel_launch(void* const* d_in, const int* in_sizes, int n_in,
                              void* d_out, int out_size)
{
    (void)in_sizes; (void)n_in; (void)out_size;
    const float* x     = (const float*)d_in[0];
    const float* enc   = (const float*)d_in[1];
    const float* Wq1 = (const float*)d_in[4];  const float* bq1 = (const float*)d_in[5];
    const float* Wk1 = (const float*)d_in[6];  const float* bk1 = (const float*)d_in[7];
    const float* Wv1 = (const float*)d_in[8];  const float* bv1 = (const float*)d_in[9];
    const float* Wo1 = (const float*)d_in[10]; const float* bo1 = (const float*)d_in[11];
    const float* Wq2 = (const float*)d_in[12]; const float* bq2 = (const float*)d_in[13];
    const float* Wk2 = (const float*)d_in[14]; const float* bk2 = (const float*)d_in[15];
    const float* Wv2 = (const float*)d_in[16]; const float* bv2 = (const float*)d_in[17];
    const float* Wo2 = (const float*)d_in[18]; const float* bo2 = (const float*)d_in[19];
    const float* Wf1 = (const float*)d_in[20]; const float* bf1 = (const float*)d_in[21];
    const float* Wf2 = (const float*)d_in[22]; const float* bf2 = (const float*)d_in[23];
    const float* g1  = (const float*)d_in[24]; const float* be1 = (const float*)d_in[25];
    const float* g2  = (const float*)d_in[26]; const float* be2 = (const float*)d_in[27];
    const float* g3  = (const float*)d_in[28]; const float* be3 = (const float*)d_in[29];
    float* out = (float*)d_out;

    float *o, *x1, *x2;
    __half *xh, *ench, *qh, *kh, *vh, *ah, *x1h, *x2h, *ffh;
    __half *wq1h, *wk1h, *wv1h, *wo1h, *wq2h, *wk2h, *wv2h, *wo2h, *wf1h, *wf2h;
    cudaGetSymbolAddress((void**)&o,    g_o);
    cudaGetSymbolAddress((void**)&x1,   g_x1);
    cudaGetSymbolAddress((void**)&x2,   g_x2);
    cudaGetSymbolAddress((void**)&xh,   g_xh);
    cudaGetSymbolAddress((void**)&ench, g_ench);
    cudaGetSymbolAddress((void**)&qh,   g_qh);
    cudaGetSymbolAddress((void**)&kh,   g_kh);
    cudaGetSymbolAddress((void**)&vh,   g_vh);
    cudaGetSymbolAddress((void**)&ah,   g_ah);
    cudaGetSymbolAddress((void**)&x1h,  g_x1h);
    cudaGetSymbolAddress((void**)&x2h,  g_x2h);
    cudaGetSymbolAddress((void**)&ffh,  g_ffh);
    cudaGetSymbolAddress((void**)&wq1h, g_wq1h);
    cudaGetSymbolAddress((void**)&wk1h, g_wk1h);
    cudaGetSymbolAddress((void**)&wv1h, g_wv1h);
    cudaGetSymbolAddress((void**)&wo1h, g_wo1h);
    cudaGetSymbolAddress((void**)&wq2h, g_wq2h);
    cudaGetSymbolAddress((void**)&wk2h, g_wk2h);
    cudaGetSymbolAddress((void**)&wv2h, g_wv2h);
    cudaGetSymbolAddress((void**)&wo2h, g_wo2h);
    cudaGetSymbolAddress((void**)&wf1h, g_wf1h);
    cudaGetSymbolAddress((void**)&wf2h, g_wf2h);

    // ---- conversions (weights + x + enc) ----
    ConvTab tab;
    const int DD = DMODEL * DMODEL, DH = ROWS * DMODEL, DW = DFF * DMODEL;
    tab.e[0]  = {x,   xh,   DH};  tab.e[1]  = {enc, ench, DH};
    tab.e[2]  = {Wq1, wq1h, DD};  tab.e[3]  = {Wk1, wk1h, DD};
    tab.e[4]  = {Wv1, wv1h, DD};  tab.e[5]  = {Wo1, wo1h, DD};
    tab.e[6]  = {Wq2, wq2h, DD};  tab.e[7]  = {Wk2, wk2h, DD};
    tab.e[8]  = {Wv2, wv2h, DD};  tab.e[9]  = {Wo2, wo2h, DD};
    tab.e[10] = {Wf1, wf1h, DW};  tab.e[11] = {Wf2, wf2h, DW};
    conv_many<<<dim3(DW / (256 * 4), N_CONV), 256>>>(tab);

    const int FLASH_SMEM = (128 + 64 + 64 + 128) * FSH * 2;  // 55296 B
    cudaFuncSetAttribute(flash_attn, cudaFuncAttributeMaxDynamicSharedMemorySize, FLASH_SMEM);
    const int GEMM_SMEM = 6 * GTILE * 2;                     // 61440 B
    cudaFuncSetAttribute(gemm_f16, cudaFuncAttributeMaxDynamicSharedMemorySize, GEMM_SMEM);

    const dim3 gProj(DMODEL / 128, ROWS / 128);   // (8, 32)
    const dim3 gFF1 (DFF    / 128, ROWS / 128);   // (32, 32)
    const dim3 gAttn(SEQ / 128, HEADS, BATCH);    // (16, 16, 2)
    const float QS = 0.125f;   // 1/sqrt(64) folded into Q

    // ---- self attention ----
    gemm_f16<<<gProj, 256, GEMM_SMEM>>>(xh, wq1h, bq1, nullptr, qh, ROWS, DMODEL, DMODEL, 0, QS);
    gemm_f16<<<gProj, 256, GEMM_SMEM>>>(xh, wk1h, bk1, nullptr, kh, ROWS, DMODEL, DMODEL, 0, 1.f);
    gemm_f16<<<gProj, 256, GEMM_SMEM>>>(xh, wv1h, bv1, nullptr, vh, ROWS, DMODEL, DMODEL, 0, 1.f);
    flash_attn<<<gAttn, 256, FLASH_SMEM>>>(qh, kh, vh, ah, SEQ, SEQ, 1);
    gemm_f16<<<gProj, 256, GEMM_SMEM>>>(ah, wo1h, bo1, o, nullptr, ROWS, DMODEL, DMODEL, 0, 1.f);
    add_ln<<<ROWS, 256>>>(x, o, g1, be1, x1, x1h);

    // ---- cross attention ----
    gemm_f16<<<gProj, 256, GEMM_SMEM>>>(x1h,  wq2h, bq2, nullptr, qh, ROWS, DMODEL, DMODEL, 0, QS);
    gemm_f16<<<gProj, 256, GEMM_SMEM>>>(ench, wk2h, bk2, nullptr, kh, ROWS, DMODEL, DMODEL, 0, 1.f);
    gemm_f16<<<gProj, 256, GEMM_SMEM>>>(ench, wv2h, bv2, nullptr, vh, ROWS, DMODEL, DMODEL, 0, 1.f);
    flash_attn<<<gAttn, 256, FLASH_SMEM>>>(qh, kh, vh, ah, SEQ, SEQ, 0);
    gemm_f16<<<gProj, 256, GEMM_SMEM>>>(ah, wo2h, bo2, o, nullptr, ROWS, DMODEL, DMODEL, 0, 1.f);
    add_ln<<<ROWS, 256>>>(x1, o, g2, be2, x2, x2h);

    // ---- FFN ----
    gemm_f16<<<gFF1, 256, GEMM_SMEM>>>(x2h, wf1h, bf1, nullptr, ffh, ROWS, DFF, DMODEL, 1, 1.f);
    gemm_f16<<<gProj, 256, GEMM_SMEM>>>(ffh, wf2h, bf2, o, nullptr, ROWS, DMODEL, DFF, 0, 1.f);
    add_ln<<<ROWS, 256>>>(x2, o, g3, be3, out, nullptr);
}

// round 7
// speedup vs baseline: 5.6950x; 1.0388x over previous
#include <cuda_runtime.h>
#include <cuda_fp16.h>
#include <math.h>
#include <stdint.h>

// Problem constants
#define BATCH 2
#define SEQ   2048
#define DMODEL 1024
#define HEADS 16
#define DKH   64
#define DFF   4096
#define ROWS  (BATCH * SEQ)   // 4096

// ---------------- scratch (static device globals; no allocation) -------------
__device__ float  g_o  [ROWS * DMODEL];
__device__ float  g_x1 [ROWS * DMODEL];
__device__ float  g_x2 [ROWS * DMODEL];
__device__ float  g_bqkv1[3 * DMODEL];
__device__ float  g_bqkv2[3 * DMODEL];

__device__ __half g_xh   [ROWS * DMODEL];
__device__ __half g_ench [ROWS * DMODEL];
__device__ __half g_qkvh [(size_t)ROWS * 3 * DMODEL];
__device__ __half g_ah   [ROWS * DMODEL];
__device__ __half g_x1h  [ROWS * DMODEL];
__device__ __half g_x2h  [ROWS * DMODEL];
__device__ __half g_ffh  [(size_t)ROWS * DFF];
__device__ __half g_wqkv1h[3 * DMODEL * DMODEL];
__device__ __half g_wqkv2h[3 * DMODEL * DMODEL];
__device__ __half g_wo1h [DMODEL * DMODEL];
__device__ __half g_wo2h [DMODEL * DMODEL];
__device__ __half g_wf1h [DFF * DMODEL];
__device__ __half g_wf2h [DMODEL * DFF];

__device__ __forceinline__ unsigned smem_u32(const void* p) {
    return (unsigned)__cvta_generic_to_shared(p);
}

// =============================================================================
// Batched f32 -> f16 conversion with per-entry scale (Q weights get 1/8)
// =============================================================================
#define N_CONV 12
struct ConvEnt { const float* s; __half* d; int n; float sc; };
struct ConvTab { ConvEnt e[N_CONV]; };

__global__ __launch_bounds__(256) void conv_many(ConvTab t) {
    ConvEnt ent = t.e[blockIdx.y];
    const int i = (blockIdx.x * 256 + threadIdx.x) * 4;
    if (i >= ent.n) return;
    float4 f = *(const float4*)(ent.s + i);
    *(__half2*)(ent.d + i)     = __floats2half2_rn(f.x * ent.sc, f.y * ent.sc);
    *(__half2*)(ent.d + i + 2) = __floats2half2_rn(f.z * ent.sc, f.w * ent.sc);
}

__global__ __launch_bounds__(256) void bias_concat(
    const float* bq1, const float* bk1, const float* bv1,
    const float* bq2, const float* bk2, const float* bv2,
    float* b1, float* b2)
{
    const int i = blockIdx.x * 256 + threadIdx.x;   // 0..3071
    if (i < DMODEL)          { b1[i] = bq1[i] * 0.125f;       b2[i] = bq2[i] * 0.125f; }
    else if (i < 2 * DMODEL) { b1[i] = bk1[i - DMODEL];       b2[i] = bk2[i - DMODEL]; }
    else                     { b1[i] = bv1[i - 2 * DMODEL];   b2[i] = bv2[i - 2 * DMODEL]; }
}

// =============================================================================
// FP16 tensor-core GEMM:  C[M,N] = A[M,K] * B[N,K]^T + bias[N]
// 128x128 tile, K-tile 64, 2-stage cp.async, 256 threads (8 warps 2m x 4n),
// warp tile 64x32, mma.m16n8k16. Smem stride 72 halves (conflict-free).
// =============================================================================
#define GLD 72                        // halves per smem row (64 data + 8 pad)
#define GTILE (128 * GLD)             // halves per stage per matrix

__global__ __launch_bounds__(256, 2) void gemm_f16(
    const __half* __restrict__ A, const __half* __restrict__ B,
    const float* __restrict__ bias, float* __restrict__ C32,
    __half* __restrict__ C16,
    int M, int N, int K, int relu)
{
    extern __shared__ __half shh[];
    __half* As = shh;                 // 2 stages
    __half* Bs = shh + 2 * GTILE;     // 2 stages

    const int tid  = threadIdx.x;
    const int lane = tid & 31;
    const int w    = tid >> 5;
    const int wm   = w & 1;
    const int wn   = w >> 1;
    const int m0 = blockIdx.y * 128;
    const int n0 = blockIdx.x * 128;

    A += (size_t)m0 * K;
    B += (size_t)n0 * K;

    float acc[4][4][4];
#pragma unroll
    for (int mi = 0; mi < 4; mi++)
#pragma unroll
        for (int ni = 0; ni < 4; ni++)
#pragma unroll
            for (int r = 0; r < 4; r++) acc[mi][ni][r] = 0.f;

    // loader: 1024 16B-chunks per matrix per stage; 4 per thread per matrix
    const int lrow = tid >> 3;          // 0..31, +32 per chunk group
    const int lc   = (tid & 7) * 8;     // 0..56

    auto load_tile = [&](int st, int k0) {
        unsigned Adst = smem_u32(As + st * GTILE + lrow * GLD + lc);
        unsigned Bdst = smem_u32(Bs + st * GTILE + lrow * GLD + lc);
        const __half* Asrc = A + (size_t)lrow * K + k0 + lc;
        const __half* Bsrc = B + (size_t)lrow * K + k0 + lc;
#pragma unroll
        for (int i = 0; i < 4; i++) {
            asm volatile("cp.async.cg.shared.global [%0], [%1], 16;\n"
                         :: "r"(Adst + i * 32 * GLD * 2), "l"(Asrc + (size_t)i * 32 * K));
            asm volatile("cp.async.cg.shared.global [%0], [%1], 16;\n"
                         :: "r"(Bdst + i * 32 * GLD * 2), "l"(Bsrc + (size_t)i * 32 * K));
        }
    };

    const int a_row = wm * 64 + (lane & 15);   // + mi*16
    const int b_row = wn * 32 + (lane & 15);   // + pj*16
    const int colh  = (lane >> 4) * 8;         // + ks*16

    load_tile(0, 0);
    asm volatile("cp.async.commit_group;\n");

    const int nk = K >> 6;
    for (int kt = 0; kt < nk; kt++) {
        if (kt + 1 < nk) {
            load_tile((kt + 1) & 1, (kt + 1) << 6);
            asm volatile("cp.async.commit_group;\n");
            asm volatile("cp.async.wait_group 1;\n");
        } else {
            asm volatile("cp.async.wait_group 0;\n");
        }
        __syncthreads();

        const __half* Ab = As + (kt & 1) * GTILE;
        const __half* Bb = Bs + (kt & 1) * GTILE;
        const unsigned abase = smem_u32(Ab + a_row * GLD + colh);
        const unsigned bbase = smem_u32(Bb + b_row * GLD + colh);

#pragma unroll
        for (int ks = 0; ks < 4; ks++) {
            uint32_t af[4][4], bf[4][2];
#pragma unroll
            for (int mi = 0; mi < 4; mi++) {
                asm volatile(
                    "ldmatrix.sync.aligned.m8n8.x4.shared.b16 {%0,%1,%2,%3}, [%4];\n"
                    : "=r"(af[mi][0]), "=r"(af[mi][1]), "=r"(af[mi][2]), "=r"(af[mi][3])
                    : "r"(abase + mi * 16 * GLD * 2 + ks * 32));
            }
#pragma unroll
            for (int pj = 0; pj < 2; pj++) {
                uint32_t r0, r1, r2, r3;
                asm volatile(
                    "ldmatrix.sync.aligned.m8n8.x4.shared.b16 {%0,%1,%2,%3}, [%4];\n"
                    : "=r"(r0), "=r"(r1), "=r"(r2), "=r"(r3)
                    : "r"(bbase + pj * 16 * GLD * 2 + ks * 32));
                bf[2 * pj][0] = r0; bf[2 * pj][1] = r2;
                bf[2 * pj + 1][0] = r1; bf[2 * pj + 1][1] = r3;
            }
#pragma unroll
            for (int mi = 0; mi < 4; mi++)
#pragma unroll
                for (int ni = 0; ni < 4; ni++) {
                    asm volatile(
                        "mma.sync.aligned.m16n8k16.row.col.f32.f16.f16.f32 "
                        "{%0,%1,%2,%3}, {%4,%5,%6,%7}, {%8,%9}, {%0,%1,%2,%3};\n"
                        : "+f"(acc[mi][ni][0]), "+f"(acc[mi][ni][1]),
                          "+f"(acc[mi][ni][2]), "+f"(acc[mi][ni][3])
                        : "r"(af[mi][0]), "r"(af[mi][1]), "r"(af[mi][2]), "r"(af[mi][3]),
                          "r"(bf[ni][0]), "r"(bf[ni][1]));
                }
        }
        __syncthreads();
    }

#pragma unroll
    for (int mi = 0; mi < 4; mi++) {
        const int row = m0 + wm * 64 + mi * 16 + (lane >> 2);
#pragma unroll
        for (int ni = 0; ni < 4; ni++) {
            const int col = n0 + wn * 32 + ni * 8 + 2 * (lane & 3);
            const float bv0 = bias[col], bv1 = bias[col + 1];
            float v0 = acc[mi][ni][0] + bv0;
            float v1 = acc[mi][ni][1] + bv1;
            float v2 = acc[mi][ni][2] + bv0;
            float v3 = acc[mi][ni][3] + bv1;
            if (relu) {
                v0 = fmaxf(v0, 0.f); v1 = fmaxf(v1, 0.f);
                v2 = fmaxf(v2, 0.f); v3 = fmaxf(v3, 0.f);
            }
            if (C32) {
                *(float2*)(C32 + (size_t)row * N + col)       = make_float2(v0, v1);
                *(float2*)(C32 + (size_t)(row + 8) * N + col) = make_float2(v2, v3);
            }
            if (C16) {
                *(__half2*)(C16 + (size_t)row * N + col)       = __floats2half2_rn(v0, v1);
                *(__half2*)(C16 + (size_t)(row + 8) * N + col) = __floats2half2_rn(v2, v3);
            }
        }
    }
}

// =============================================================================
// FP16 tensor-core flash attention. Bq=128 (8 warps x 16 rows), Bkv=64, DK=64.
// Q pre-scaled (1/8 folded into Wq). Row strides ldq/ldkv support the fused
// QKV buffer. Smem stride 72 halves (conflict-free ldmatrix).
// =============================================================================
#define FSH 72

__global__ __launch_bounds__(256, 2) void flash_attn(
    const __half* __restrict__ Qg, const __half* __restrict__ Kg,
    const __half* __restrict__ Vg, __half* __restrict__ Og,
    int qlen, int kvlen, int ldq, int ldkv, int causal)
{
    extern __shared__ __half smh[];
    __half* Qs = smh;                 // 128 x 64 (q  x d)
    __half* Ks = Qs + 128 * FSH;      // 64  x 64 (kv x d)
    __half* Vt = Ks + 64 * FSH;       // 64  x 64 (d  x kv)  transposed
    __half* Ps = Vt + 64 * FSH;       // 128 x 64 (q  x kv)

    const int tid  = threadIdx.x;
    const int lane = tid & 31;
    const int w    = tid >> 5;
    const int qrow = w * 16;
    const int r0   = lane >> 2;
    const int b  = blockIdx.z;
    const int h  = blockIdx.y;
    const int q0 = blockIdx.x * 128;

    const __half* Qb = Qg + (size_t)b * qlen  * ldq  + h * DKH;
    const __half* Kb = Kg + (size_t)b * kvlen * ldkv + h * DKH;
    const __half* Vb = Vg + (size_t)b * kvlen * ldkv + h * DKH;

    const int a_row = qrow + (lane & 15);
    const int colh  = (lane >> 4) * 8;
    const int b_rowc = lane & 15;

#pragma unroll
    for (int it = 0; it < 4; it++) {
        const int idx = tid + it * 256;
        const int r = idx >> 3;
        const int c = (idx & 7) * 8;
        *(uint4*)(Qs + r * FSH + c) = *(const uint4*)(Qb + (size_t)(q0 + r) * ldq + c);
    }

    float m_i[2], l_i[2], o[8][4];
    m_i[0] = m_i[1] = -1e30f;
    l_i[0] = l_i[1] = 0.f;
#pragma unroll
    for (int ni = 0; ni < 8; ni++)
#pragma unroll
        for (int r = 0; r < 4; r++) o[ni][r] = 0.f;

    const int kv_end = causal ? min(kvlen, q0 + 128) : kvlen;

    for (int kv0 = 0; kv0 < kv_end; kv0 += 64) {
        __syncthreads();
#pragma unroll
        for (int it = 0; it < 2; it++) {
            const int idx = tid + it * 256;
            const int r = idx >> 3;
            const int c = (idx & 7) * 8;
            *(uint4*)(Ks + r * FSH + c) = *(const uint4*)(Kb + (size_t)(kv0 + r) * ldkv + c);
        }
#pragma unroll
        for (int it = 0; it < 2; it++) {
            const int idx = tid + it * 256;
            const int r  = idx & 63;
            const int c8 = (idx >> 6) * 8;
            uint4 raw = *(const uint4*)(Vb + (size_t)(kv0 + r) * ldkv + c8);
            const __half* hv = (const __half*)&raw;
#pragma unroll
            for (int i = 0; i < 8; i++) Vt[(c8 + i) * FSH + r] = hv[i];
        }
        __syncthreads();

        if (causal && kv0 > q0 + qrow + 15) continue;

        // ---- S = Q K^T ----
        float s[8][4];
#pragma unroll
        for (int ni = 0; ni < 8; ni++)
#pragma unroll
            for (int r = 0; r < 4; r++) s[ni][r] = 0.f;

#pragma unroll
        for (int ks = 0; ks < 4; ks++) {
            uint32_t af[4], bf[8][2];
            asm volatile(
                "ldmatrix.sync.aligned.m8n8.x4.shared.b16 {%0,%1,%2,%3}, [%4];\n"
                : "=r"(af[0]), "=r"(af[1]), "=r"(af[2]), "=r"(af[3])
                : "r"(smem_u32(Qs + a_row * FSH + ks * 16 + colh)));
#pragma unroll
            for (int pj = 0; pj < 4; pj++) {
                uint32_t r0r, r1r, r2r, r3r;
                asm volatile(
                    "ldmatrix.sync.aligned.m8n8.x4.shared.b16 {%0,%1,%2,%3}, [%4];\n"
                    : "=r"(r0r), "=r"(r1r), "=r"(r2r), "=r"(r3r)
                    : "r"(smem_u32(Ks + (pj * 16 + b_rowc) * FSH + ks * 16 + colh)));
                bf[2 * pj][0] = r0r; bf[2 * pj][1] = r2r;
                bf[2 * pj + 1][0] = r1r; bf[2 * pj + 1][1] = r3r;
            }
#pragma unroll
            for (int ni = 0; ni < 8; ni++) {
                asm volatile(
                    "mma.sync.aligned.m16n8k16.row.col.f32.f16.f16.f32 "
                    "{%0,%1,%2,%3}, {%4,%5,%6,%7}, {%8,%9}, {%0,%1,%2,%3};\n"
                    : "+f"(s[ni][0]), "+f"(s[ni][1]), "+f"(s[ni][2]), "+f"(s[ni][3])
                    : "r"(af[0]), "r"(af[1]), "r"(af[2]), "r"(af[3]),
                      "r"(bf[ni][0]), "r"(bf[ni][1]));
            }
        }

        // ---- causal mask ----
        if (causal && kv0 + 63 > q0 + qrow) {
            const int row0 = q0 + qrow + r0;
            const int colb = kv0 + 2 * (lane & 3);
#pragma unroll
            for (int ni = 0; ni < 8; ni++) {
                const int c = colb + ni * 8;
                if (c     > row0    ) s[ni][0] = -1e30f;
                if (c + 1 > row0    ) s[ni][1] = -1e30f;
                if (c     > row0 + 8) s[ni][2] = -1e30f;
                if (c + 1 > row0 + 8) s[ni][3] = -1e30f;
            }
        }

        // ---- online softmax; P -> smem (fp16) ----
#pragma unroll
        for (int hh = 0; hh < 2; hh++) {
            float mt = -1e30f;
#pragma unroll
            for (int ni = 0; ni < 8; ni++)
                mt = fmaxf(mt, fmaxf(s[ni][2 * hh], s[ni][2 * hh + 1]));
            mt = fmaxf(mt, __shfl_xor_sync(0xffffffffu, mt, 1));
            mt = fmaxf(mt, __shfl_xor_sync(0xffffffffu, mt, 2));
            const float mn = fmaxf(m_i[hh], mt);
            const float corr = __expf(m_i[hh] - mn);
            m_i[hh] = mn;
            float rs = 0.f;
            __half* Prow = Ps + (qrow + r0 + 8 * hh) * FSH + 2 * (lane & 3);
#pragma unroll
            for (int ni = 0; ni < 8; ni++) {
                const float p0 = __expf(s[ni][2 * hh]     - mn);
                const float p1 = __expf(s[ni][2 * hh + 1] - mn);
                rs += p0 + p1;
                *(__half2*)(Prow + ni * 8) = __floats2half2_rn(p0, p1);
            }
            rs += __shfl_xor_sync(0xffffffffu, rs, 1);
            rs += __shfl_xor_sync(0xffffffffu, rs, 2);
            l_i[hh] = l_i[hh] * corr + rs;
#pragma unroll
            for (int ni = 0; ni < 8; ni++) {
                o[ni][2 * hh]     *= corr;
                o[ni][2 * hh + 1] *= corr;
            }
        }
        __syncwarp();  // P rows are warp-private

        // ---- O += P * V ----
#pragma unroll
        for (int ks = 0; ks < 4; ks++) {
            uint32_t af[4], bf[8][2];
            asm volatile(
                "ldmatrix.sync.aligned.m8n8.x4.shared.b16 {%0,%1,%2,%3}, [%4];\n"
                : "=r"(af[0]), "=r"(af[1]), "=r"(af[2]), "=r"(af[3])
                : "r"(smem_u32(Ps + a_row * FSH + ks * 16 + colh)));
#pragma unroll
            for (int pj = 0; pj < 4; pj++) {
                uint32_t r0r, r1r, r2r, r3r;
                asm volatile(
                    "ldmatrix.sync.aligned.m8n8.x4.shared.b16 {%0,%1,%2,%3}, [%4];\n"
                    : "=r"(r0r), "=r"(r1r), "=r"(r2r), "=r"(r3r)
                    : "r"(smem_u32(Vt + (pj * 16 + b_rowc) * FSH + ks * 16 + colh)));
                bf[2 * pj][0] = r0r; bf[2 * pj][1] = r2r;
                bf[2 * pj + 1][0] = r1r; bf[2 * pj + 1][1] = r3r;
            }
#pragma unroll
            for (int ni = 0; ni < 8; ni++) {
                asm volatile(
                    "mma.sync.aligned.m16n8k16.row.col.f32.f16.f16.f32 "
                    "{%0,%1,%2,%3}, {%4,%5,%6,%7}, {%8,%9}, {%0,%1,%2,%3};\n"
                    : "+f"(o[ni][0]), "+f"(o[ni][1]), "+f"(o[ni][2]), "+f"(o[ni][3])
                    : "r"(af[0]), "r"(af[1]), "r"(af[2]), "r"(af[3]),
                      "r"(bf[ni][0]), "r"(bf[ni][1]));
            }
        }
    }

    // ---- normalize + write (fp16) ----
    const float inv0 = 1.f / l_i[0];
    const float inv1 = 1.f / l_i[1];
    const int row0 = q0 + qrow + r0;
    __half* O0 = Og + ((size_t)b * qlen + row0) * DMODEL + h * DKH + 2 * (lane & 3);
    __half* O1 = O0 + (size_t)8 * DMODEL;
#pragma unroll
    for (int ni = 0; ni < 8; ni++) {
        *(__half2*)(O0 + ni * 8) = __floats2half2_rn(o[ni][0] * inv0, o[ni][1] * inv0);
        *(__half2*)(O1 + ni * 8) = __floats2half2_rn(o[ni][2] * inv1, o[ni][3] * inv1);
    }
}

// =============================================================================
// out = LayerNorm(x + y) * g + be ; optional fp16 copy
// =============================================================================
__global__ __launch_bounds__(256) void add_ln(
    const float* __restrict__ X, const float* __restrict__ Y,
    const float* __restrict__ g, const float* __restrict__ be,
    float* __restrict__ Out, __half* __restrict__ Out16)
{
    __shared__ float red[8];
    const int row = blockIdx.x;
    const int tid = threadIdx.x;
    const float* xr = X + (size_t)row * DMODEL;
    const float* yr = Y + (size_t)row * DMODEL;

    float v[4];
    float s = 0.f;
#pragma unroll
    for (int c = 0; c < 4; c++) {
        const int idx = tid + 256 * c;
        v[c] = xr[idx] + yr[idx];
        s += v[c];
    }
#pragma unroll
    for (int off = 16; off >= 1; off >>= 1) s += __shfl_xor_sync(0xffffffffu, s, off);
    if ((tid & 31) == 0) red[tid >> 5] = s;
    __syncthreads();
    if (tid < 32) {
        float t = (tid < 8) ? red[tid] : 0.f;
#pragma unroll
        for (int off = 4; off >= 1; off >>= 1) t += __shfl_xor_sync(0xffffffffu, t, off);
        if (tid == 0) red[0] = t;
    }
    __syncthreads();
    const float mu = red[0] * (1.f / DMODEL);
    __syncthreads();

    float sq = 0.f;
#pragma unroll
    for (int c = 0; c < 4; c++) {
        const float d = v[c] - mu;
        sq += d * d;
    }
#pragma unroll
    for (int off = 16; off >= 1; off >>= 1) sq += __shfl_xor_sync(0xffffffffu, sq, off);
    if ((tid & 31) == 0) red[tid >> 5] = sq;
    __syncthreads();
    if (tid < 32) {
        float t = (tid < 8) ? red[tid] : 0.f;
#pragma unroll
        for (int off = 4; off >= 1; off >>= 1) t += __shfl_xor_sync(0xffffffffu, t, off);
        if (tid == 0) red[0] = t;
    }
    __syncthreads();
    const float rstd = rsqrtf(red[0] * (1.f / DMODEL) + 1e-5f);

    float* orow = Out + (size_t)row * DMODEL;
#pragma unroll
    for (int c = 0; c < 4; c++) {
        const int idx = tid + 256 * c;
        const float val = (v[c] - mu) * rstd * g[idx] + be[idx];
        orow[idx] = val;
        if (Out16) Out16[(size_t)row * DMODEL + idx] = __float2half(val);
    }
}

// =============================================================================
// Launch
// =============================================================================
extern "C" void kernel_launch(void* const* d_in, const int* in_sizes, int n_in,
                              void* d_out, int out_size)
{
    (void)in_sizes; (void)n_in; (void)out_size;
    const float* x     = (const float*)d_in[0];
    const float* enc   = (const float*)d_in[1];
    const float* Wq1 = (const float*)d_in[4];  const float* bq1 = (const float*)d_in[5];
    const float* Wk1 = (const float*)d_in[6];  const float* bk1 = (const float*)d_in[7];
    const float* Wv1 = (const float*)d_in[8];  const float* bv1 = (const float*)d_in[9];
    const float* Wo1 = (const float*)d_in[10]; const float* bo1 = (const float*)d_in[11];
    const float* Wq2 = (const float*)d_in[12]; const float* bq2 = (const float*)d_in[13];
    const float* Wk2 = (const float*)d_in[14]; const float* bk2 = (const float*)d_in[15];
    const float* Wv2 = (const float*)d_in[16]; const float* bv2 = (const float*)d_in[17];
    const float* Wo2 = (const float*)d_in[18]; const float* bo2 = (const float*)d_in[19];
    const float* Wf1 = (const float*)d_in[20]; const float* bf1 = (const float*)d_in[21];
    const float* Wf2 = (const float*)d_in[22]; const float* bf2 = (const float*)d_in[23];
    const float* g1  = (const float*)d_in[24]; const float* be1 = (const float*)d_in[25];
    const float* g2  = (const float*)d_in[26]; const float* be2 = (const float*)d_in[27];
    const float* g3  = (const float*)d_in[28]; const float* be3 = (const float*)d_in[29];
    float* out = (float*)d_out;

    float *o, *x1, *x2, *bqkv1, *bqkv2;
    __half *xh, *ench, *qkvh, *ah, *x1h, *x2h, *ffh;
    __half *wqkv1h, *wqkv2h, *wo1h, *wo2h, *wf1h, *wf2h;
    cudaGetSymbolAddress((void**)&o,      g_o);
    cudaGetSymbolAddress((void**)&x1,     g_x1);
    cudaGetSymbolAddress((void**)&x2,     g_x2);
    cudaGetSymbolAddress((void**)&bqkv1,  g_bqkv1);
    cudaGetSymbolAddress((void**)&bqkv2,  g_bqkv2);
    cudaGetSymbolAddress((void**)&xh,     g_xh);
    cudaGetSymbolAddress((void**)&ench,   g_ench);
    cudaGetSymbolAddress((void**)&qkvh,   g_qkvh);
    cudaGetSymbolAddress((void**)&ah,     g_ah);
    cudaGetSymbolAddress((void**)&x1h,    g_x1h);
    cudaGetSymbolAddress((void**)&x2h,    g_x2h);
    cudaGetSymbolAddress((void**)&ffh,    g_ffh);
    cudaGetSymbolAddress((void**)&wqkv1h, g_wqkv1h);
    cudaGetSymbolAddress((void**)&wqkv2h, g_wqkv2h);
    cudaGetSymbolAddress((void**)&wo1h,   g_wo1h);
    cudaGetSymbolAddress((void**)&wo2h,   g_wo2h);
    cudaGetSymbolAddress((void**)&wf1h,   g_wf1h);
    cudaGetSymbolAddress((void**)&wf2h,   g_wf2h);

    // ---- conversions ----
    ConvTab tab;
    const int DD = DMODEL * DMODEL, DH = ROWS * DMODEL, DW = DFF * DMODEL;
    tab.e[0]  = {x,   xh,   DH, 1.f};
    tab.e[1]  = {enc, ench, DH, 1.f};
    tab.e[2]  = {Wq1, wqkv1h,          DD, 0.125f};   // 1/sqrt(64) folded
    tab.e[3]  = {Wk1, wqkv1h + DD,     DD, 1.f};
    tab.e[4]  = {Wv1, wqkv1h + 2 * DD, DD, 1.f};
    tab.e[5]  = {Wo1, wo1h, DD, 1.f};
    tab.e[6]  = {Wq2, wqkv2h,          DD, 0.125f};
    tab.e[7]  = {Wk2, wqkv2h + DD,     DD, 1.f};
    tab.e[8]  = {Wv2, wqkv2h + 2 * DD, DD, 1.f};
    tab.e[9]  = {Wo2, wo2h, DD, 1.f};
    tab.e[10] = {Wf1, wf1h, DW, 1.f};
    tab.e[11] = {Wf2, wf2h, DW, 1.f};
    conv_many<<<dim3(DW / (256 * 4), N_CONV), 256>>>(tab);
    bias_concat<<<12, 256>>>(bq1, bk1, bv1, bq2, bk2, bv2, bqkv1, bqkv2);

    const int FLASH_SMEM = (128 + 64 + 64 + 128) * FSH * 2;  // 55296 B
    cudaFuncSetAttribute(flash_attn, cudaFuncAttributeMaxDynamicSharedMemorySize, FLASH_SMEM);
    const int GEMM_SMEM = 4 * GTILE * 2;                     // 73728 B
    cudaFuncSetAttribute(gemm_f16, cudaFuncAttributeMaxDynamicSharedMemorySize, GEMM_SMEM);

    const dim3 gQKV (3 * DMODEL / 128, ROWS / 128);  // (24, 32)
    const dim3 gProj(DMODEL / 128, ROWS / 128);      // (8, 32)
    const dim3 gFF1 (DFF    / 128, ROWS / 128);      // (32, 32)
    const dim3 gAttn(SEQ / 128, HEADS, BATCH);       // (16, 16, 2)
    const int LD3 = 3 * DMODEL;

    // ---- self attention ----
    gemm_f16<<<gQKV, 256, GEMM_SMEM>>>(xh, wqkv1h, bqkv1, nullptr, qkvh, ROWS, LD3, DMODEL, 0);
    flash_attn<<<gAttn, 256, FLASH_SMEM>>>(qkvh, qkvh + DMODEL, qkvh + 2 * DMODEL, ah,
                                           SEQ, SEQ, LD3, LD3, 1);
    gemm_f16<<<gProj, 256, GEMM_SMEM>>>(ah, wo1h, bo1, o, nullptr, ROWS, DMODEL, DMODEL, 0);
    add_ln<<<ROWS, 256>>>(x, o, g1, be1, x1, x1h);

    // ---- cross attention ----
    // Q from x1h must use Wq2 slice; K/V from ench. Launch QKV gemm on x1h for Q
    // and on ench for K/V via two partial-N launches over the same fused weights.
    {
        // Q part: N-range [0,1024) of wqkv2
        gemm_f16<<<gProj, 256, GEMM_SMEM>>>(x1h, wqkv2h, bqkv2, nullptr, qkvh,
                                            ROWS, LD3, DMODEL, 0);
        // overwrite K/V parts using enc: grid over N-range [1024,3072)
        dim3 gKV(2 * DMODEL / 128, ROWS / 128);      // (16, 32)
        gemm_f16<<<gKV, 256, GEMM_SMEM>>>(ench, wqkv2h + (size_t)DMODEL * DMODEL,
                                          bqkv2 + DMODEL, nullptr, qkvh + DMODEL,
                                          ROWS, LD3, DMODEL, 0);
    }
    flash_attn<<<gAttn, 256, FLASH_SMEM>>>(qkvh, qkvh + DMODEL, qkvh + 2 * DMODEL, ah,
                                           SEQ, SEQ, LD3, LD3, 0);
    gemm_f16<<<gProj, 256, GEMM_SMEM>>>(ah, wo2h, bo2, o, nullptr, ROWS, DMODEL, DMODEL, 0);
    add_ln<<<ROWS, 256>>>(x1, o, g2, be2, x2, x2h);

    // ---- FFN ----
    gemm_f16<<<gFF1, 256, GEMM_SMEM>>>(x2h, wf1h, bf1, nullptr, ffh, ROWS, DFF, DMODEL, 1);
    gemm_f16<<<gProj, 256, GEMM_SMEM>>>(ffh, wf2h, bf2, o, nullptr, ROWS, DMODEL, DFF, 0);
    add_ln<<<ROWS, 256>>>(x2, o, g3, be3, out, nullptr);
}

// round 8
// speedup vs baseline: 6.3852x; 1.1212x over previous
#include <cuda_runtime.h>
#include <cuda_fp16.h>
#include <math.h>
#include <stdint.h>

// Problem constants
#define BATCH 2
#define SEQ   2048
#define DMODEL 1024
#define HEADS 16
#define DKH   64
#define DFF   4096
#define ROWS  (BATCH * SEQ)   // 4096

// ---------------- scratch (static device globals; no allocation) -------------
__device__ float  g_o  [ROWS * DMODEL];
__device__ float  g_x1 [ROWS * DMODEL];
__device__ float  g_x2 [ROWS * DMODEL];
__device__ float  g_bqkv1[3 * DMODEL];
__device__ float  g_bqkv2[3 * DMODEL];

__device__ __half g_xh   [ROWS * DMODEL];
__device__ __half g_ench [ROWS * DMODEL];
__device__ __half g_qkvh [(size_t)ROWS * 3 * DMODEL];
__device__ __half g_ah   [ROWS * DMODEL];
__device__ __half g_x1h  [ROWS * DMODEL];
__device__ __half g_x2h  [ROWS * DMODEL];
__device__ __half g_ffh  [(size_t)ROWS * DFF];
__device__ __half g_wqkv1h[3 * DMODEL * DMODEL];
__device__ __half g_wqkv2h[3 * DMODEL * DMODEL];
__device__ __half g_wo1h [DMODEL * DMODEL];
__device__ __half g_wo2h [DMODEL * DMODEL];
__device__ __half g_wf1h [DFF * DMODEL];
__device__ __half g_wf2h [DMODEL * DFF];

__device__ __forceinline__ unsigned smem_u32(const void* p) {
    return (unsigned)__cvta_generic_to_shared(p);
}
__device__ __forceinline__ uint32_t h2_u32(__half2 h) {
    return *(uint32_t*)&h;
}

// =============================================================================
// Batched f32 -> f16 conversion with per-entry scale (Q weights get 1/8)
// =============================================================================
#define N_CONV 12
struct ConvEnt { const float* s; __half* d; int n; float sc; };
struct ConvTab { ConvEnt e[N_CONV]; };

__global__ __launch_bounds__(256) void conv_many(ConvTab t) {
    ConvEnt ent = t.e[blockIdx.y];
    const int i = (blockIdx.x * 256 + threadIdx.x) * 4;
    if (i >= ent.n) return;
    float4 f = *(const float4*)(ent.s + i);
    *(__half2*)(ent.d + i)     = __floats2half2_rn(f.x * ent.sc, f.y * ent.sc);
    *(__half2*)(ent.d + i + 2) = __floats2half2_rn(f.z * ent.sc, f.w * ent.sc);
}

__global__ __launch_bounds__(256) void bias_concat(
    const float* bq1, const float* bk1, const float* bv1,
    const float* bq2, const float* bk2, const float* bv2,
    float* b1, float* b2)
{
    const int i = blockIdx.x * 256 + threadIdx.x;   // 0..3071
    if (i < DMODEL)          { b1[i] = bq1[i] * 0.125f;       b2[i] = bq2[i] * 0.125f; }
    else if (i < 2 * DMODEL) { b1[i] = bk1[i - DMODEL];       b2[i] = bk2[i - DMODEL]; }
    else                     { b1[i] = bv1[i - 2 * DMODEL];   b2[i] = bv2[i - 2 * DMODEL]; }
}

// =============================================================================
// FP16 tensor-core GEMM:  C[M,N] = A[M,K] * B[N,K]^T + bias[N]
// 128x128 tile, K-tile 64, 2-stage cp.async, 256 threads (8 warps 2m x 4n),
// warp tile 64x32, mma.m16n8k16. Smem stride 72 halves (conflict-free).
// =============================================================================
#define GLD 72                        // halves per smem row (64 data + 8 pad)
#define GTILE (128 * GLD)             // halves per stage per matrix

__global__ __launch_bounds__(256, 2) void gemm_f16(
    const __half* __restrict__ A, const __half* __restrict__ B,
    const float* __restrict__ bias, float* __restrict__ C32,
    __half* __restrict__ C16,
    int M, int N, int K, int relu)
{
    extern __shared__ __half shh[];
    __half* As = shh;                 // 2 stages
    __half* Bs = shh + 2 * GTILE;     // 2 stages

    const int tid  = threadIdx.x;
    const int lane = tid & 31;
    const int w    = tid >> 5;
    const int wm   = w & 1;
    const int wn   = w >> 1;
    const int m0 = blockIdx.y * 128;
    const int n0 = blockIdx.x * 128;

    A += (size_t)m0 * K;
    B += (size_t)n0 * K;

    float acc[4][4][4];
#pragma unroll
    for (int mi = 0; mi < 4; mi++)
#pragma unroll
        for (int ni = 0; ni < 4; ni++)
#pragma unroll
            for (int r = 0; r < 4; r++) acc[mi][ni][r] = 0.f;

    const int lrow = tid >> 3;          // 0..31, +32 per chunk group
    const int lc   = (tid & 7) * 8;     // 0..56

    auto load_tile = [&](int st, int k0) {
        unsigned Adst = smem_u32(As + st * GTILE + lrow * GLD + lc);
        unsigned Bdst = smem_u32(Bs + st * GTILE + lrow * GLD + lc);
        const __half* Asrc = A + (size_t)lrow * K + k0 + lc;
        const __half* Bsrc = B + (size_t)lrow * K + k0 + lc;
#pragma unroll
        for (int i = 0; i < 4; i++) {
            asm volatile("cp.async.cg.shared.global [%0], [%1], 16;\n"
                         :: "r"(Adst + i * 32 * GLD * 2), "l"(Asrc + (size_t)i * 32 * K));
            asm volatile("cp.async.cg.shared.global [%0], [%1], 16;\n"
                         :: "r"(Bdst + i * 32 * GLD * 2), "l"(Bsrc + (size_t)i * 32 * K));
        }
    };

    const int a_row = wm * 64 + (lane & 15);   // + mi*16
    const int b_row = wn * 32 + (lane & 15);   // + pj*16
    const int colh  = (lane >> 4) * 8;         // + ks*16

    load_tile(0, 0);
    asm volatile("cp.async.commit_group;\n");

    const int nk = K >> 6;
    for (int kt = 0; kt < nk; kt++) {
        if (kt + 1 < nk) {
            load_tile((kt + 1) & 1, (kt + 1) << 6);
            asm volatile("cp.async.commit_group;\n");
            asm volatile("cp.async.wait_group 1;\n");
        } else {
            asm volatile("cp.async.wait_group 0;\n");
        }
        __syncthreads();

        const __half* Ab = As + (kt & 1) * GTILE;
        const __half* Bb = Bs + (kt & 1) * GTILE;
        const unsigned abase = smem_u32(Ab + a_row * GLD + colh);
        const unsigned bbase = smem_u32(Bb + b_row * GLD + colh);

#pragma unroll
        for (int ks = 0; ks < 4; ks++) {
            uint32_t af[4][4], bf[4][2];
#pragma unroll
            for (int mi = 0; mi < 4; mi++) {
                asm volatile(
                    "ldmatrix.sync.aligned.m8n8.x4.shared.b16 {%0,%1,%2,%3}, [%4];\n"
                    : "=r"(af[mi][0]), "=r"(af[mi][1]), "=r"(af[mi][2]), "=r"(af[mi][3])
                    : "r"(abase + mi * 16 * GLD * 2 + ks * 32));
            }
#pragma unroll
            for (int pj = 0; pj < 2; pj++) {
                uint32_t r0, r1, r2, r3;
                asm volatile(
                    "ldmatrix.sync.aligned.m8n8.x4.shared.b16 {%0,%1,%2,%3}, [%4];\n"
                    : "=r"(r0), "=r"(r1), "=r"(r2), "=r"(r3)
                    : "r"(bbase + pj * 16 * GLD * 2 + ks * 32));
                bf[2 * pj][0] = r0; bf[2 * pj][1] = r2;
                bf[2 * pj + 1][0] = r1; bf[2 * pj + 1][1] = r3;
            }
#pragma unroll
            for (int mi = 0; mi < 4; mi++)
#pragma unroll
                for (int ni = 0; ni < 4; ni++) {
                    asm volatile(
                        "mma.sync.aligned.m16n8k16.row.col.f32.f16.f16.f32 "
                        "{%0,%1,%2,%3}, {%4,%5,%6,%7}, {%8,%9}, {%0,%1,%2,%3};\n"
                        : "+f"(acc[mi][ni][0]), "+f"(acc[mi][ni][1]),
                          "+f"(acc[mi][ni][2]), "+f"(acc[mi][ni][3])
                        : "r"(af[mi][0]), "r"(af[mi][1]), "r"(af[mi][2]), "r"(af[mi][3]),
                          "r"(bf[ni][0]), "r"(bf[ni][1]));
                }
        }
        __syncthreads();
    }

#pragma unroll
    for (int mi = 0; mi < 4; mi++) {
        const int row = m0 + wm * 64 + mi * 16 + (lane >> 2);
#pragma unroll
        for (int ni = 0; ni < 4; ni++) {
            const int col = n0 + wn * 32 + ni * 8 + 2 * (lane & 3);
            const float bv0 = bias[col], bv1 = bias[col + 1];
            float v0 = acc[mi][ni][0] + bv0;
            float v1 = acc[mi][ni][1] + bv1;
            float v2 = acc[mi][ni][2] + bv0;
            float v3 = acc[mi][ni][3] + bv1;
            if (relu) {
                v0 = fmaxf(v0, 0.f); v1 = fmaxf(v1, 0.f);
                v2 = fmaxf(v2, 0.f); v3 = fmaxf(v3, 0.f);
            }
            if (C32) {
                *(float2*)(C32 + (size_t)row * N + col)       = make_float2(v0, v1);
                *(float2*)(C32 + (size_t)(row + 8) * N + col) = make_float2(v2, v3);
            }
            if (C16) {
                *(__half2*)(C16 + (size_t)row * N + col)       = __floats2half2_rn(v0, v1);
                *(__half2*)(C16 + (size_t)(row + 8) * N + col) = __floats2half2_rn(v2, v3);
            }
        }
    }
}

// =============================================================================
// FP16 flash attention, FA2-style. Bq=128 (8 warps x 16 rows), Bkv=64, DK=64.
// P kept in registers (acc->A-frag identity); V consumed via ldmatrix.trans;
// K/V tiles double-buffered with cp.async. Smem stride 72 (conflict-free).
// =============================================================================
#define FSH 72
#define KV_STG (2 * 64 * FSH)        // halves per KV stage (K tile + V tile)

__global__ __launch_bounds__(256, 2) void flash_attn(
    const __half* __restrict__ Qg, const __half* __restrict__ Kg,
    const __half* __restrict__ Vg, __half* __restrict__ Og,
    int qlen, int kvlen, int ldq, int ldkv, int causal)
{
    extern __shared__ __half smh[];
    __half* Qs  = smh;                // 128 x FSH
    __half* KVs = smh + 128 * FSH;    // 2 stages x (K 64xFSH, V 64xFSH)

    const int tid  = threadIdx.x;
    const int lane = tid & 31;
    const int w    = tid >> 5;
    const int qrow = w * 16;
    const int r0   = lane >> 2;
    const int b  = blockIdx.z;
    const int h  = blockIdx.y;
    const int q0 = blockIdx.x * 128;

    const __half* Qb = Qg + (size_t)b * qlen  * ldq  + h * DKH;
    const __half* Kb = Kg + (size_t)b * kvlen * ldkv + h * DKH;
    const __half* Vb = Vg + (size_t)b * kvlen * ldkv + h * DKH;

    const int a_row  = qrow + (lane & 15);
    const int colh   = (lane >> 4) * 8;
    const int b_rowc = lane & 15;

    // Q tile: plain vector loads (once per block)
#pragma unroll
    for (int it = 0; it < 4; it++) {
        const int idx = tid + it * 256;
        const int r = idx >> 3;
        const int c = (idx & 7) * 8;
        *(uint4*)(Qs + r * FSH + c) = *(const uint4*)(Qb + (size_t)(q0 + r) * ldq + c);
    }

    // K/V loader: 512 16B-chunks each, 2 per thread each, via cp.async
    const int lrow = tid >> 3;          // 0..31 (+32)
    const int lc   = (tid & 7) * 8;
    auto load_kv = [&](int st, int kv0) {
        __half* Ks = KVs + st * KV_STG;
        __half* Vs = Ks + 64 * FSH;
        unsigned kd = smem_u32(Ks + lrow * FSH + lc);
        unsigned vd = smem_u32(Vs + lrow * FSH + lc);
        const __half* ksrc = Kb + (size_t)(kv0 + lrow) * ldkv + lc;
        const __half* vsrc = Vb + (size_t)(kv0 + lrow) * ldkv + lc;
        asm volatile("cp.async.cg.shared.global [%0], [%1], 16;\n" :: "r"(kd), "l"(ksrc));
        asm volatile("cp.async.cg.shared.global [%0], [%1], 16;\n"
                     :: "r"(kd + 32 * FSH * 2), "l"(ksrc + (size_t)32 * ldkv));
        asm volatile("cp.async.cg.shared.global [%0], [%1], 16;\n" :: "r"(vd), "l"(vsrc));
        asm volatile("cp.async.cg.shared.global [%0], [%1], 16;\n"
                     :: "r"(vd + 32 * FSH * 2), "l"(vsrc + (size_t)32 * ldkv));
    };

    float m_i[2], l_i[2], o[8][4];
    m_i[0] = m_i[1] = -1e30f;
    l_i[0] = l_i[1] = 0.f;
#pragma unroll
    for (int ni = 0; ni < 8; ni++)
#pragma unroll
        for (int r = 0; r < 4; r++) o[ni][r] = 0.f;

    const int kv_end = causal ? min(kvlen, q0 + 128) : kvlen;
    const int niter  = (kv_end + 63) >> 6;

    load_kv(0, 0);
    asm volatile("cp.async.commit_group;\n");

    for (int it = 0; it < niter; it++) {
        const int kv0 = it << 6;
        if (it + 1 < niter) {
            load_kv((it + 1) & 1, kv0 + 64);
            asm volatile("cp.async.commit_group;\n");
            asm volatile("cp.async.wait_group 1;\n");
        } else {
            asm volatile("cp.async.wait_group 0;\n");
        }
        __syncthreads();

        const __half* Ks = KVs + (it & 1) * KV_STG;
        const __half* Vs = Ks + 64 * FSH;

        if (!(causal && kv0 > q0 + qrow + 15)) {
            // ---- S = Q K^T ----
            float s[8][4];
#pragma unroll
            for (int ni = 0; ni < 8; ni++)
#pragma unroll
                for (int r = 0; r < 4; r++) s[ni][r] = 0.f;

#pragma unroll
            for (int ks = 0; ks < 4; ks++) {
                uint32_t af[4], bf[8][2];
                asm volatile(
                    "ldmatrix.sync.aligned.m8n8.x4.shared.b16 {%0,%1,%2,%3}, [%4];\n"
                    : "=r"(af[0]), "=r"(af[1]), "=r"(af[2]), "=r"(af[3])
                    : "r"(smem_u32(Qs + a_row * FSH + ks * 16 + colh)));
#pragma unroll
                for (int pj = 0; pj < 4; pj++) {
                    uint32_t r0r, r1r, r2r, r3r;
                    asm volatile(
                        "ldmatrix.sync.aligned.m8n8.x4.shared.b16 {%0,%1,%2,%3}, [%4];\n"
                        : "=r"(r0r), "=r"(r1r), "=r"(r2r), "=r"(r3r)
                        : "r"(smem_u32(Ks + (pj * 16 + b_rowc) * FSH + ks * 16 + colh)));
                    bf[2 * pj][0] = r0r; bf[2 * pj][1] = r2r;
                    bf[2 * pj + 1][0] = r1r; bf[2 * pj + 1][1] = r3r;
                }
#pragma unroll
                for (int ni = 0; ni < 8; ni++) {
                    asm volatile(
                        "mma.sync.aligned.m16n8k16.row.col.f32.f16.f16.f32 "
                        "{%0,%1,%2,%3}, {%4,%5,%6,%7}, {%8,%9}, {%0,%1,%2,%3};\n"
                        : "+f"(s[ni][0]), "+f"(s[ni][1]), "+f"(s[ni][2]), "+f"(s[ni][3])
                        : "r"(af[0]), "r"(af[1]), "r"(af[2]), "r"(af[3]),
                          "r"(bf[ni][0]), "r"(bf[ni][1]));
                }
            }

            // ---- causal mask ----
            if (causal && kv0 + 63 > q0 + qrow) {
                const int row0 = q0 + qrow + r0;
                const int colb = kv0 + 2 * (lane & 3);
#pragma unroll
                for (int ni = 0; ni < 8; ni++) {
                    const int c = colb + ni * 8;
                    if (c     > row0    ) s[ni][0] = -1e30f;
                    if (c + 1 > row0    ) s[ni][1] = -1e30f;
                    if (c     > row0 + 8) s[ni][2] = -1e30f;
                    if (c + 1 > row0 + 8) s[ni][3] = -1e30f;
                }
            }

            // ---- online softmax; P stays in registers (packed fp16) ----
            uint32_t ph0[8], ph1[8];   // rows r0 / r0+8
#pragma unroll
            for (int hh = 0; hh < 2; hh++) {
                float mt = -1e30f;
#pragma unroll
                for (int ni = 0; ni < 8; ni++)
                    mt = fmaxf(mt, fmaxf(s[ni][2 * hh], s[ni][2 * hh + 1]));
                mt = fmaxf(mt, __shfl_xor_sync(0xffffffffu, mt, 1));
                mt = fmaxf(mt, __shfl_xor_sync(0xffffffffu, mt, 2));
                const float mn = fmaxf(m_i[hh], mt);
                const float corr = __expf(m_i[hh] - mn);
                m_i[hh] = mn;
                float rs = 0.f;
#pragma unroll
                for (int ni = 0; ni < 8; ni++) {
                    const float p0 = __expf(s[ni][2 * hh]     - mn);
                    const float p1 = __expf(s[ni][2 * hh + 1] - mn);
                    rs += p0 + p1;
                    const uint32_t packed = h2_u32(__floats2half2_rn(p0, p1));
                    if (hh == 0) ph0[ni] = packed; else ph1[ni] = packed;
                }
                rs += __shfl_xor_sync(0xffffffffu, rs, 1);
                rs += __shfl_xor_sync(0xffffffffu, rs, 2);
                l_i[hh] = l_i[hh] * corr + rs;
#pragma unroll
                for (int ni = 0; ni < 8; ni++) {
                    o[ni][2 * hh]     *= corr;
                    o[ni][2 * hh + 1] *= corr;
                }
            }

            // ---- O += P * V  (A from registers, B via ldmatrix.trans on V) ----
#pragma unroll
            for (int ks = 0; ks < 4; ks++) {
                const uint32_t af0 = ph0[2 * ks],     af1 = ph1[2 * ks];
                const uint32_t af2 = ph0[2 * ks + 1], af3 = ph1[2 * ks + 1];
#pragma unroll
                for (int pj = 0; pj < 4; pj++) {
                    uint32_t b0, b1, b2, b3;
                    asm volatile(
                        "ldmatrix.sync.aligned.m8n8.x4.trans.shared.b16 {%0,%1,%2,%3}, [%4];\n"
                        : "=r"(b0), "=r"(b1), "=r"(b2), "=r"(b3)
                        : "r"(smem_u32(Vs + (ks * 16 + b_rowc) * FSH + colh + pj * 16)));
                    // matrices: (kv0-7,d0-7)=b0lo, (kv8-15,d0-7)=b1lo, (kv0-7,d8-15), (kv8-15,d8-15)
                    asm volatile(
                        "mma.sync.aligned.m16n8k16.row.col.f32.f16.f16.f32 "
                        "{%0,%1,%2,%3}, {%4,%5,%6,%7}, {%8,%9}, {%0,%1,%2,%3};\n"
                        : "+f"(o[2 * pj][0]), "+f"(o[2 * pj][1]),
                          "+f"(o[2 * pj][2]), "+f"(o[2 * pj][3])
                        : "r"(af0), "r"(af1), "r"(af2), "r"(af3), "r"(b0), "r"(b1));
                    asm volatile(
                        "mma.sync.aligned.m16n8k16.row.col.f32.f16.f16.f32 "
                        "{%0,%1,%2,%3}, {%4,%5,%6,%7}, {%8,%9}, {%0,%1,%2,%3};\n"
                        : "+f"(o[2 * pj + 1][0]), "+f"(o[2 * pj + 1][1]),
                          "+f"(o[2 * pj + 1][2]), "+f"(o[2 * pj + 1][3])
                        : "r"(af0), "r"(af1), "r"(af2), "r"(af3), "r"(b2), "r"(b3));
                }
            }
        }
        __syncthreads();
    }

    // ---- normalize + write (fp16) ----
    const float inv0 = 1.f / l_i[0];
    const float inv1 = 1.f / l_i[1];
    const int row0 = q0 + qrow + r0;
    __half* O0 = Og + ((size_t)b * qlen + row0) * DMODEL + h * DKH + 2 * (lane & 3);
    __half* O1 = O0 + (size_t)8 * DMODEL;
#pragma unroll
    for (int ni = 0; ni < 8; ni++) {
        *(__half2*)(O0 + ni * 8) = __floats2half2_rn(o[ni][0] * inv0, o[ni][1] * inv0);
        *(__half2*)(O1 + ni * 8) = __floats2half2_rn(o[ni][2] * inv1, o[ni][3] * inv1);
    }
}

// =============================================================================
// out = LayerNorm(x + y) * g + be ; optional fp16 copy
// =============================================================================
__global__ __launch_bounds__(256) void add_ln(
    const float* __restrict__ X, const float* __restrict__ Y,
    const float* __restrict__ g, const float* __restrict__ be,
    float* __restrict__ Out, __half* __restrict__ Out16)
{
    __shared__ float red[8];
    const int row = blockIdx.x;
    const int tid = threadIdx.x;
    const float* xr = X + (size_t)row * DMODEL;
    const float* yr = Y + (size_t)row * DMODEL;

    float v[4];
    float s = 0.f;
#pragma unroll
    for (int c = 0; c < 4; c++) {
        const int idx = tid + 256 * c;
        v[c] = xr[idx] + yr[idx];
        s += v[c];
    }
#pragma unroll
    for (int off = 16; off >= 1; off >>= 1) s += __shfl_xor_sync(0xffffffffu, s, off);
    if ((tid & 31) == 0) red[tid >> 5] = s;
    __syncthreads();
    if (tid < 32) {
        float t = (tid < 8) ? red[tid] : 0.f;
#pragma unroll
        for (int off = 4; off >= 1; off >>= 1) t += __shfl_xor_sync(0xffffffffu, t, off);
        if (tid == 0) red[0] = t;
    }
    __syncthreads();
    const float mu = red[0] * (1.f / DMODEL);
    __syncthreads();

    float sq = 0.f;
#pragma unroll
    for (int c = 0; c < 4; c++) {
        const float d = v[c] - mu;
        sq += d * d;
    }
#pragma unroll
    for (int off = 16; off >= 1; off >>= 1) sq += __shfl_xor_sync(0xffffffffu, sq, off);
    if ((tid & 31) == 0) red[tid >> 5] = sq;
    __syncthreads();
    if (tid < 32) {
        float t = (tid < 8) ? red[tid] : 0.f;
#pragma unroll
        for (int off = 4; off >= 1; off >>= 1) t += __shfl_xor_sync(0xffffffffu, t, off);
        if (tid == 0) red[0] = t;
    }
    __syncthreads();
    const float rstd = rsqrtf(red[0] * (1.f / DMODEL) + 1e-5f);

    float* orow = Out + (size_t)row * DMODEL;
#pragma unroll
    for (int c = 0; c < 4; c++) {
        const int idx = tid + 256 * c;
        const float val = (v[c] - mu) * rstd * g[idx] + be[idx];
        orow[idx] = val;
        if (Out16) Out16[(size_t)row * DMODEL + idx] = __float2half(val);
    }
}

// =============================================================================
// Launch
// =============================================================================
extern "C" void kernel_launch(void* const* d_in, const int* in_sizes, int n_in,
                              void* d_out, int out_size)
{
    (void)in_sizes; (void)n_in; (void)out_size;
    const float* x     = (const float*)d_in[0];
    const float* enc   = (const float*)d_in[1];
    const float* Wq1 = (const float*)d_in[4];  const float* bq1 = (const float*)d_in[5];
    const float* Wk1 = (const float*)d_in[6];  const float* bk1 = (const float*)d_in[7];
    const float* Wv1 = (const float*)d_in[8];  const float* bv1 = (const float*)d_in[9];
    const float* Wo1 = (const float*)d_in[10]; const float* bo1 = (const float*)d_in[11];
    const float* Wq2 = (const float*)d_in[12]; const float* bq2 = (const float*)d_in[13];
    const float* Wk2 = (const float*)d_in[14]; const float* bk2 = (const float*)d_in[15];
    const float* Wv2 = (const float*)d_in[16]; const float* bv2 = (const float*)d_in[17];
    const float* Wo2 = (const float*)d_in[18]; const float* bo2 = (const float*)d_in[19];
    const float* Wf1 = (const float*)d_in[20]; const float* bf1 = (const float*)d_in[21];
    const float* Wf2 = (const float*)d_in[22]; const float* bf2 = (const float*)d_in[23];
    const float* g1  = (const float*)d_in[24]; const float* be1 = (const float*)d_in[25];
    const float* g2  = (const float*)d_in[26]; const float* be2 = (const float*)d_in[27];
    const float* g3  = (const float*)d_in[28]; const float* be3 = (const float*)d_in[29];
    float* out = (float*)d_out;

    float *o, *x1, *x2, *bqkv1, *bqkv2;
    __half *xh, *ench, *qkvh, *ah, *x1h, *x2h, *ffh;
    __half *wqkv1h, *wqkv2h, *wo1h, *wo2h, *wf1h, *wf2h;
    cudaGetSymbolAddress((void**)&o,      g_o);
    cudaGetSymbolAddress((void**)&x1,     g_x1);
    cudaGetSymbolAddress((void**)&x2,     g_x2);
    cudaGetSymbolAddress((void**)&bqkv1,  g_bqkv1);
    cudaGetSymbolAddress((void**)&bqkv2,  g_bqkv2);
    cudaGetSymbolAddress((void**)&xh,     g_xh);
    cudaGetSymbolAddress((void**)&ench,   g_ench);
    cudaGetSymbolAddress((void**)&qkvh,   g_qkvh);
    cudaGetSymbolAddress((void**)&ah,     g_ah);
    cudaGetSymbolAddress((void**)&x1h,    g_x1h);
    cudaGetSymbolAddress((void**)&x2h,    g_x2h);
    cudaGetSymbolAddress((void**)&ffh,    g_ffh);
    cudaGetSymbolAddress((void**)&wqkv1h, g_wqkv1h);
    cudaGetSymbolAddress((void**)&wqkv2h, g_wqkv2h);
    cudaGetSymbolAddress((void**)&wo1h,   g_wo1h);
    cudaGetSymbolAddress((void**)&wo2h,   g_wo2h);
    cudaGetSymbolAddress((void**)&wf1h,   g_wf1h);
    cudaGetSymbolAddress((void**)&wf2h,   g_wf2h);

    // ---- conversions ----
    ConvTab tab;
    const int DD = DMODEL * DMODEL, DH = ROWS * DMODEL, DW = DFF * DMODEL;
    tab.e[0]  = {x,   xh,   DH, 1.f};
    tab.e[1]  = {enc, ench, DH, 1.f};
    tab.e[2]  = {Wq1, wqkv1h,          DD, 0.125f};   // 1/sqrt(64) folded
    tab.e[3]  = {Wk1, wqkv1h + DD,     DD, 1.f};
    tab.e[4]  = {Wv1, wqkv1h + 2 * DD, DD, 1.f};
    tab.e[5]  = {Wo1, wo1h, DD, 1.f};
    tab.e[6]  = {Wq2, wqkv2h,          DD, 0.125f};
    tab.e[7]  = {Wk2, wqkv2h + DD,     DD, 1.f};
    tab.e[8]  = {Wv2, wqkv2h + 2 * DD, DD, 1.f};
    tab.e[9]  = {Wo2, wo2h, DD, 1.f};
    tab.e[10] = {Wf1, wf1h, DW, 1.f};
    tab.e[11] = {Wf2, wf2h, DW, 1.f};
    conv_many<<<dim3(DW / (256 * 4), N_CONV), 256>>>(tab);
    bias_concat<<<12, 256>>>(bq1, bk1, bv1, bq2, bk2, bv2, bqkv1, bqkv2);

    const int FLASH_SMEM = (128 * FSH + 2 * KV_STG) * 2;     // 55296 B
    cudaFuncSetAttribute(flash_attn, cudaFuncAttributeMaxDynamicSharedMemorySize, FLASH_SMEM);
    const int GEMM_SMEM = 4 * GTILE * 2;                     // 73728 B
    cudaFuncSetAttribute(gemm_f16, cudaFuncAttributeMaxDynamicSharedMemorySize, GEMM_SMEM);

    const dim3 gQKV (3 * DMODEL / 128, ROWS / 128);  // (24, 32)
    const dim3 gProj(DMODEL / 128, ROWS / 128);      // (8, 32)
    const dim3 gFF1 (DFF    / 128, ROWS / 128);      // (32, 32)
    const dim3 gAttn(SEQ / 128, HEADS, BATCH);       // (16, 16, 2)
    const int LD3 = 3 * DMODEL;

    // ---- self attention ----
    gemm_f16<<<gQKV, 256, GEMM_SMEM>>>(xh, wqkv1h, bqkv1, nullptr, qkvh, ROWS, LD3, DMODEL, 0);
    flash_attn<<<gAttn, 256, FLASH_SMEM>>>(qkvh, qkvh + DMODEL, qkvh + 2 * DMODEL, ah,
                                           SEQ, SEQ, LD3, LD3, 1);
    gemm_f16<<<gProj, 256, GEMM_SMEM>>>(ah, wo1h, bo1, o, nullptr, ROWS, DMODEL, DMODEL, 0);
    add_ln<<<ROWS, 256>>>(x, o, g1, be1, x1, x1h);

    // ---- cross attention ----
    gemm_f16<<<gProj, 256, GEMM_SMEM>>>(x1h, wqkv2h, bqkv2, nullptr, qkvh,
                                        ROWS, LD3, DMODEL, 0);
    {
        dim3 gKV(2 * DMODEL / 128, ROWS / 128);      // (16, 32)
        gemm_f16<<<gKV, 256, GEMM_SMEM>>>(ench, wqkv2h + (size_t)DMODEL * DMODEL,
                                          bqkv2 + DMODEL, nullptr, qkvh + DMODEL,
                                          ROWS, LD3, DMODEL, 0);
    }
    flash_attn<<<gAttn, 256, FLASH_SMEM>>>(qkvh, qkvh + DMODEL, qkvh + 2 * DMODEL, ah,
                                           SEQ, SEQ, LD3, LD3, 0);
    gemm_f16<<<gProj, 256, GEMM_SMEM>>>(ah, wo2h, bo2, o, nullptr, ROWS, DMODEL, DMODEL, 0);
    add_ln<<<ROWS, 256>>>(x1, o, g2, be2, x2, x2h);

    // ---- FFN ----
    gemm_f16<<<gFF1, 256, GEMM_SMEM>>>(x2h, wf1h, bf1, nullptr, ffh, ROWS, DFF, DMODEL, 1);
    gemm_f16<<<gProj, 256, GEMM_SMEM>>>(ffh, wf2h, bf2, o, nullptr, ROWS, DMODEL, DFF, 0);
    add_ln<<<ROWS, 256>>>(x2, o, g3, be3, out, nullptr);
}

// round 11
// speedup vs baseline: 6.7817x; 1.0621x over previous
#include <cuda_runtime.h>
#include <cuda_fp16.h>
#include <math.h>
#include <stdint.h>

// Problem constants
#define BATCH 2
#define SEQ   2048
#define DMODEL 1024
#define HEADS 16
#define DKH   64
#define DFF   4096
#define ROWS  (BATCH * SEQ)   // 4096

// ---------------- scratch (static device globals; no allocation) -------------
__device__ float  g_o  [ROWS * DMODEL];
__device__ float  g_x1 [ROWS * DMODEL];
__device__ float  g_x2 [ROWS * DMODEL];
__device__ float  g_bqkv1[3 * DMODEL];
__device__ float  g_bqkv2[3 * DMODEL];

__device__ __half g_xh   [ROWS * DMODEL];
__device__ __half g_ench [ROWS * DMODEL];
__device__ __half g_qkvh [(size_t)ROWS * 3 * DMODEL];
__device__ __half g_qkv2h[(size_t)ROWS * 3 * DMODEL];
__device__ __half g_ah   [ROWS * DMODEL];
__device__ __half g_x1h  [ROWS * DMODEL];
__device__ __half g_x2h  [ROWS * DMODEL];
__device__ __half g_ffh  [(size_t)ROWS * DFF];
__device__ __half g_wqkv1h[3 * DMODEL * DMODEL];
__device__ __half g_wqkv2h[3 * DMODEL * DMODEL];
__device__ __half g_wo1h [DMODEL * DMODEL];
__device__ __half g_wo2h [DMODEL * DMODEL];
__device__ __half g_wf1h [DFF * DMODEL];
__device__ __half g_wf2h [DMODEL * DFF];

__device__ __forceinline__ unsigned smem_u32(const void* p) {
    return (unsigned)__cvta_generic_to_shared(p);
}
__device__ __forceinline__ uint32_t h2_u32(__half2 h) {
    return *(uint32_t*)&h;
}

// =============================================================================
// Batched f32 -> f16 conversion with per-entry scale (Q weights get 1/8)
// =============================================================================
#define N_CONV 12
struct ConvEnt { const float* s; __half* d; int n; float sc; };
struct ConvTab { ConvEnt e[N_CONV]; };

__global__ __launch_bounds__(256) void conv_many(ConvTab t) {
    ConvEnt ent = t.e[blockIdx.y];
    const int i = (blockIdx.x * 256 + threadIdx.x) * 4;
    if (i >= ent.n) return;
    float4 f = *(const float4*)(ent.s + i);
    *(__half2*)(ent.d + i)     = __floats2half2_rn(f.x * ent.sc, f.y * ent.sc);
    *(__half2*)(ent.d + i + 2) = __floats2half2_rn(f.z * ent.sc, f.w * ent.sc);
}

__global__ __launch_bounds__(256) void bias_concat(
    const float* bq1, const float* bk1, const float* bv1,
    const float* bq2, const float* bk2, const float* bv2,
    float* b1, float* b2)
{
    const int i = blockIdx.x * 256 + threadIdx.x;   // 0..3071
    if (i < DMODEL)          { b1[i] = bq1[i] * 0.125f;       b2[i] = bq2[i] * 0.125f; }
    else if (i < 2 * DMODEL) { b1[i] = bk1[i - DMODEL];       b2[i] = bk2[i - DMODEL]; }
    else                     { b1[i] = bv1[i - 2 * DMODEL];   b2[i] = bv2[i - 2 * DMODEL]; }
}

// =============================================================================
// FP16 tensor-core GEMM core (mma.m16n8k16), 128x128 tile, K-tile 64,
// 2-stage cp.async, 256 threads (8 warps 2m x 4n). Smem stride 72 halves.
// =============================================================================
#define GLD 72
#define GTILE (128 * GLD)

__device__ __forceinline__ void gemm_core(
    const __half* __restrict__ A, const __half* __restrict__ B,
    const float* __restrict__ bias, float* __restrict__ C32,
    __half* __restrict__ C16,
    int K, int ldc, int relu, int m0, int n0, __half* shh)
{
    __half* As = shh;
    __half* Bs = shh + 2 * GTILE;

    const int tid  = threadIdx.x;
    const int lane = tid & 31;
    const int w    = tid >> 5;
    const int wm   = w & 1;
    const int wn   = w >> 1;

    A += (size_t)m0 * K;
    B += (size_t)n0 * K;

    float acc[4][4][4];
#pragma unroll
    for (int mi = 0; mi < 4; mi++)
#pragma unroll
        for (int ni = 0; ni < 4; ni++)
#pragma unroll
            for (int r = 0; r < 4; r++) acc[mi][ni][r] = 0.f;

    const int lrow = tid >> 3;
    const int lc   = (tid & 7) * 8;

    auto load_tile = [&](int st, int k0) {
        unsigned Adst = smem_u32(As + st * GTILE + lrow * GLD + lc);
        unsigned Bdst = smem_u32(Bs + st * GTILE + lrow * GLD + lc);
        const __half* Asrc = A + (size_t)lrow * K + k0 + lc;
        const __half* Bsrc = B + (size_t)lrow * K + k0 + lc;
#pragma unroll
        for (int i = 0; i < 4; i++) {
            asm volatile("cp.async.cg.shared.global [%0], [%1], 16;\n"
                         :: "r"(Adst + i * 32 * GLD * 2), "l"(Asrc + (size_t)i * 32 * K));
            asm volatile("cp.async.cg.shared.global [%0], [%1], 16;\n"
                         :: "r"(Bdst + i * 32 * GLD * 2), "l"(Bsrc + (size_t)i * 32 * K));
        }
    };

    const int a_row = wm * 64 + (lane & 15);
    const int b_row = wn * 32 + (lane & 15);
    const int colh  = (lane >> 4) * 8;

    load_tile(0, 0);
    asm volatile("cp.async.commit_group;\n");

    const int nk = K >> 6;
    for (int kt = 0; kt < nk; kt++) {
        if (kt + 1 < nk) {
            load_tile((kt + 1) & 1, (kt + 1) << 6);
            asm volatile("cp.async.commit_group;\n");
            asm volatile("cp.async.wait_group 1;\n");
        } else {
            asm volatile("cp.async.wait_group 0;\n");
        }
        __syncthreads();

        const __half* Ab = As + (kt & 1) * GTILE;
        const __half* Bb = Bs + (kt & 1) * GTILE;
        const unsigned abase = smem_u32(Ab + a_row * GLD + colh);
        const unsigned bbase = smem_u32(Bb + b_row * GLD + colh);

#pragma unroll
        for (int ks = 0; ks < 4; ks++) {
            uint32_t af[4][4], bf[4][2];
#pragma unroll
            for (int mi = 0; mi < 4; mi++) {
                asm volatile(
                    "ldmatrix.sync.aligned.m8n8.x4.shared.b16 {%0,%1,%2,%3}, [%4];\n"
                    : "=r"(af[mi][0]), "=r"(af[mi][1]), "=r"(af[mi][2]), "=r"(af[mi][3])
                    : "r"(abase + mi * 16 * GLD * 2 + ks * 32));
            }
#pragma unroll
            for (int pj = 0; pj < 2; pj++) {
                uint32_t r0, r1, r2, r3;
                asm volatile(
                    "ldmatrix.sync.aligned.m8n8.x4.shared.b16 {%0,%1,%2,%3}, [%4];\n"
                    : "=r"(r0), "=r"(r1), "=r"(r2), "=r"(r3)
                    : "r"(bbase + pj * 16 * GLD * 2 + ks * 32));
                bf[2 * pj][0] = r0; bf[2 * pj][1] = r2;
                bf[2 * pj + 1][0] = r1; bf[2 * pj + 1][1] = r3;
            }
#pragma unroll
            for (int mi = 0; mi < 4; mi++)
#pragma unroll
                for (int ni = 0; ni < 4; ni++) {
                    asm volatile(
                        "mma.sync.aligned.m16n8k16.row.col.f32.f16.f16.f32 "
                        "{%0,%1,%2,%3}, {%4,%5,%6,%7}, {%8,%9}, {%0,%1,%2,%3};\n"
                        : "+f"(acc[mi][ni][0]), "+f"(acc[mi][ni][1]),
                          "+f"(acc[mi][ni][2]), "+f"(acc[mi][ni][3])
                        : "r"(af[mi][0]), "r"(af[mi][1]), "r"(af[mi][2]), "r"(af[mi][3]),
                          "r"(bf[ni][0]), "r"(bf[ni][1]));
                }
        }
        __syncthreads();
    }

#pragma unroll
    for (int mi = 0; mi < 4; mi++) {
        const int row = m0 + wm * 64 + mi * 16 + (lane >> 2);
#pragma unroll
        for (int ni = 0; ni < 4; ni++) {
            const int col = n0 + wn * 32 + ni * 8 + 2 * (lane & 3);
            const float bv0 = bias[col], bv1 = bias[col + 1];
            float v0 = acc[mi][ni][0] + bv0;
            float v1 = acc[mi][ni][1] + bv1;
            float v2 = acc[mi][ni][2] + bv0;
            float v3 = acc[mi][ni][3] + bv1;
            if (relu) {
                v0 = fmaxf(v0, 0.f); v1 = fmaxf(v1, 0.f);
                v2 = fmaxf(v2, 0.f); v3 = fmaxf(v3, 0.f);
            }
            if (C32) {
                *(float2*)(C32 + (size_t)row * ldc + col)       = make_float2(v0, v1);
                *(float2*)(C32 + (size_t)(row + 8) * ldc + col) = make_float2(v2, v3);
            }
            if (C16) {
                *(__half2*)(C16 + (size_t)row * ldc + col)       = __floats2half2_rn(v0, v1);
                *(__half2*)(C16 + (size_t)(row + 8) * ldc + col) = __floats2half2_rn(v2, v3);
            }
        }
    }
}

__global__ __launch_bounds__(256, 2) void gemm_f16(
    const __half* __restrict__ A, const __half* __restrict__ B,
    const float* __restrict__ bias, float* __restrict__ C32,
    __half* __restrict__ C16, int K, int ldc, int relu)
{
    extern __shared__ __half shh[];
    gemm_core(A, B, bias, C32, C16, K, ldc, relu,
              blockIdx.y * 128, blockIdx.x * 128, shh);
}

// Dual-job GEMM: job0 = self-attn QKV (xh * Wqkv1), job1 = cross-attn KV
// (ench * Wkv2). Both fp16-out, K=DMODEL, shared ldc.
__global__ __launch_bounds__(256, 2) void gemm_dual(
    const __half* __restrict__ A0, const __half* __restrict__ B0,
    const float* __restrict__ bias0, __half* __restrict__ C0,
    const __half* __restrict__ A1, const __half* __restrict__ B1,
    const float* __restrict__ bias1, __half* __restrict__ C1,
    int split, int K, int ldc)
{
    extern __shared__ __half shh[];
    const int bx = blockIdx.x;
    if (bx < split)
        gemm_core(A0, B0, bias0, nullptr, C0, K, ldc, 0,
                  blockIdx.y * 128, bx * 128, shh);
    else
        gemm_core(A1, B1, bias1, nullptr, C1, K, ldc, 0,
                  blockIdx.y * 128, (bx - split) * 128, shh);
}

// =============================================================================
// FP16 flash attention, FA2-style. Bq=64 (4 warps x 16 rows), Bkv=64, DK=64.
// 128 threads, 4 CTAs/SM. Q fragments hoisted to registers. P in registers;
// V via ldmatrix.trans; K/V double-buffered cp.async. Stride 72.
// =============================================================================
#define FSH 72
#define KV_STG (2 * 64 * FSH)        // halves per KV stage (K tile + V tile)

__global__ __launch_bounds__(128, 4) void flash_attn(
    const __half* __restrict__ Qg, const __half* __restrict__ Kg,
    const __half* __restrict__ Vg, __half* __restrict__ Og,
    int qlen, int kvlen, int ldq, int ldkv, int causal)
{
    extern __shared__ __half smh[];
    __half* Qs  = smh;                // 64 x FSH
    __half* KVs = smh + 64 * FSH;     // 2 stages x (K 64xFSH, V 64xFSH)

    const int tid  = threadIdx.x;
    const int lane = tid & 31;
    const int w    = tid >> 5;        // 0..3
    const int qrow = w * 16;
    const int r0   = lane >> 2;
    const int b  = blockIdx.z;
    const int h  = blockIdx.y;
    const int q0 = blockIdx.x * 64;

    const __half* Qb = Qg + (size_t)b * qlen  * ldq  + h * DKH;
    const __half* Kb = Kg + (size_t)b * kvlen * ldkv + h * DKH;
    const __half* Vb = Vg + (size_t)b * kvlen * ldkv + h * DKH;

    const int a_row  = qrow + (lane & 15);
    const int colh   = (lane >> 4) * 8;
    const int b_rowc = lane & 15;

    // K/V loader: 512 chunks each, 4 per thread each
    const int lrow = tid >> 3;          // 0..15 (+16 per step)
    const int lc   = (tid & 7) * 8;
    auto load_kv = [&](int st, int kv0) {
        __half* Ks = KVs + st * KV_STG;
        __half* Vs = Ks + 64 * FSH;
        unsigned kd = smem_u32(Ks + lrow * FSH + lc);
        unsigned vd = smem_u32(Vs + lrow * FSH + lc);
        const __half* ksrc = Kb + (size_t)(kv0 + lrow) * ldkv + lc;
        const __half* vsrc = Vb + (size_t)(kv0 + lrow) * ldkv + lc;
#pragma unroll
        for (int i = 0; i < 4; i++) {
            asm volatile("cp.async.cg.shared.global [%0], [%1], 16;\n"
                         :: "r"(kd + i * 16 * FSH * 2), "l"(ksrc + (size_t)i * 16 * ldkv));
            asm volatile("cp.async.cg.shared.global [%0], [%1], 16;\n"
                         :: "r"(vd + i * 16 * FSH * 2), "l"(vsrc + (size_t)i * 16 * ldkv));
        }
    };

    // Q tile: 512 chunks, 4 per thread
#pragma unroll
    for (int it = 0; it < 4; it++) {
        const int idx = tid + it * 128;
        const int r = idx >> 3;
        const int c = (idx & 7) * 8;
        *(uint4*)(Qs + r * FSH + c) = *(const uint4*)(Qb + (size_t)(q0 + r) * ldq + c);
    }

    const int kv_end = causal ? min(kvlen, q0 + 64) : kvlen;
    const int niter  = (kv_end + 63) >> 6;

    load_kv(0, 0);
    asm volatile("cp.async.commit_group;\n");

    __syncthreads();   // Q visible
    // hoist Q fragments (loop-invariant)
    uint32_t qf[4][4];
#pragma unroll
    for (int ks = 0; ks < 4; ks++) {
        asm volatile(
            "ldmatrix.sync.aligned.m8n8.x4.shared.b16 {%0,%1,%2,%3}, [%4];\n"
            : "=r"(qf[ks][0]), "=r"(qf[ks][1]), "=r"(qf[ks][2]), "=r"(qf[ks][3])
            : "r"(smem_u32(Qs + a_row * FSH + ks * 16 + colh)));
    }

    float m_i[2], l_i[2], o[8][4];
    m_i[0] = m_i[1] = -1e30f;
    l_i[0] = l_i[1] = 0.f;
#pragma unroll
    for (int ni = 0; ni < 8; ni++)
#pragma unroll
        for (int r = 0; r < 4; r++) o[ni][r] = 0.f;

    for (int it = 0; it < niter; it++) {
        const int kv0 = it << 6;
        if (it + 1 < niter) {
            load_kv((it + 1) & 1, kv0 + 64);
            asm volatile("cp.async.commit_group;\n");
            asm volatile("cp.async.wait_group 1;\n");
        } else {
            asm volatile("cp.async.wait_group 0;\n");
        }
        __syncthreads();

        const __half* Ks = KVs + (it & 1) * KV_STG;
        const __half* Vs = Ks + 64 * FSH;

        if (!(causal && kv0 > q0 + qrow + 15)) {
            // ---- S = Q K^T ----
            float s[8][4];
#pragma unroll
            for (int ni = 0; ni < 8; ni++)
#pragma unroll
                for (int r = 0; r < 4; r++) s[ni][r] = 0.f;

#pragma unroll
            for (int ks = 0; ks < 4; ks++) {
                uint32_t bf[8][2];
#pragma unroll
                for (int pj = 0; pj < 4; pj++) {
                    uint32_t r0r, r1r, r2r, r3r;
                    asm volatile(
                        "ldmatrix.sync.aligned.m8n8.x4.shared.b16 {%0,%1,%2,%3}, [%4];\n"
                        : "=r"(r0r), "=r"(r1r), "=r"(r2r), "=r"(r3r)
                        : "r"(smem_u32(Ks + (pj * 16 + b_rowc) * FSH + ks * 16 + colh)));
                    bf[2 * pj][0] = r0r; bf[2 * pj][1] = r2r;
                    bf[2 * pj + 1][0] = r1r; bf[2 * pj + 1][1] = r3r;
                }
#pragma unroll
                for (int ni = 0; ni < 8; ni++) {
                    asm volatile(
                        "mma.sync.aligned.m16n8k16.row.col.f32.f16.f16.f32 "
                        "{%0,%1,%2,%3}, {%4,%5,%6,%7}, {%8,%9}, {%0,%1,%2,%3};\n"
                        : "+f"(s[ni][0]), "+f"(s[ni][1]), "+f"(s[ni][2]), "+f"(s[ni][3])
                        : "r"(qf[ks][0]), "r"(qf[ks][1]), "r"(qf[ks][2]), "r"(qf[ks][3]),
                          "r"(bf[ni][0]), "r"(bf[ni][1]));
                }
            }

            // ---- causal mask ----
            if (causal && kv0 + 63 > q0 + qrow) {
                const int row0 = q0 + qrow + r0;
                const int colb = kv0 + 2 * (lane & 3);
#pragma unroll
                for (int ni = 0; ni < 8; ni++) {
                    const int c = colb + ni * 8;
                    if (c     > row0    ) s[ni][0] = -1e30f;
                    if (c + 1 > row0    ) s[ni][1] = -1e30f;
                    if (c     > row0 + 8) s[ni][2] = -1e30f;
                    if (c + 1 > row0 + 8) s[ni][3] = -1e30f;
                }
            }

            // ---- online softmax; P stays in registers ----
            uint32_t ph0[8], ph1[8];
#pragma unroll
            for (int hh = 0; hh < 2; hh++) {
                float mt = -1e30f;
#pragma unroll
                for (int ni = 0; ni < 8; ni++)
                    mt = fmaxf(mt, fmaxf(s[ni][2 * hh], s[ni][2 * hh + 1]));
                mt = fmaxf(mt, __shfl_xor_sync(0xffffffffu, mt, 1));
                mt = fmaxf(mt, __shfl_xor_sync(0xffffffffu, mt, 2));
                const float mn = fmaxf(m_i[hh], mt);
                const float corr = __expf(m_i[hh] - mn);
                m_i[hh] = mn;
                float rs = 0.f;
#pragma unroll
                for (int ni = 0; ni < 8; ni++) {
                    const float p0 = __expf(s[ni][2 * hh]     - mn);
                    const float p1 = __expf(s[ni][2 * hh + 1] - mn);
                    rs += p0 + p1;
                    const uint32_t packed = h2_u32(__floats2half2_rn(p0, p1));
                    if (hh == 0) ph0[ni] = packed; else ph1[ni] = packed;
                }
                rs += __shfl_xor_sync(0xffffffffu, rs, 1);
                rs += __shfl_xor_sync(0xffffffffu, rs, 2);
                l_i[hh] = l_i[hh] * corr + rs;
#pragma unroll
                for (int ni = 0; ni < 8; ni++) {
                    o[ni][2 * hh]     *= corr;
                    o[ni][2 * hh + 1] *= corr;
                }
            }

            // ---- O += P * V ----
#pragma unroll
            for (int ks = 0; ks < 4; ks++) {
                const uint32_t af0 = ph0[2 * ks],     af1 = ph1[2 * ks];
                const uint32_t af2 = ph0[2 * ks + 1], af3 = ph1[2 * ks + 1];
#pragma unroll
                for (int pj = 0; pj < 4; pj++) {
                    uint32_t b0, b1, b2, b3;
                    asm volatile(
                        "ldmatrix.sync.aligned.m8n8.x4.trans.shared.b16 {%0,%1,%2,%3}, [%4];\n"
                        : "=r"(b0), "=r"(b1), "=r"(b2), "=r"(b3)
                        : "r"(smem_u32(Vs + (ks * 16 + b_rowc) * FSH + colh + pj * 16)));
                    asm volatile(
                        "mma.sync.aligned.m16n8k16.row.col.f32.f16.f16.f32 "
                        "{%0,%1,%2,%3}, {%4,%5,%6,%7}, {%8,%9}, {%0,%1,%2,%3};\n"
                        : "+f"(o[2 * pj][0]), "+f"(o[2 * pj][1]),
                          "+f"(o[2 * pj][2]), "+f"(o[2 * pj][3])
                        : "r"(af0), "r"(af1), "r"(af2), "r"(af3), "r"(b0), "r"(b1));
                    asm volatile(
                        "mma.sync.aligned.m16n8k16.row.col.f32.f16.f16.f32 "
                        "{%0,%1,%2,%3}, {%4,%5,%6,%7}, {%8,%9}, {%0,%1,%2,%3};\n"
                        : "+f"(o[2 * pj + 1][0]), "+f"(o[2 * pj + 1][1]),
                          "+f"(o[2 * pj + 1][2]), "+f"(o[2 * pj + 1][3])
                        : "r"(af0), "r"(af1), "r"(af2), "r"(af3), "r"(b2), "r"(b3));
                }
            }
        }
        __syncthreads();
    }

    // ---- normalize + write (fp16) ----
    const float inv0 = 1.f / l_i[0];
    const float inv1 = 1.f / l_i[1];
    const int row0 = q0 + qrow + r0;
    __half* O0 = Og + ((size_t)b * qlen + row0) * DMODEL + h * DKH + 2 * (lane & 3);
    __half* O1 = O0 + (size_t)8 * DMODEL;
#pragma unroll
    for (int ni = 0; ni < 8; ni++) {
        *(__half2*)(O0 + ni * 8) = __floats2half2_rn(o[ni][0] * inv0, o[ni][1] * inv0);
        *(__half2*)(O1 + ni * 8) = __floats2half2_rn(o[ni][2] * inv1, o[ni][3] * inv1);
    }
}

// =============================================================================
// out = LayerNorm(x + y) * g + be ; optional fp16 copy
// =============================================================================
__global__ __launch_bounds__(256) void add_ln(
    const float* __restrict__ X, const float* __restrict__ Y,
    const float* __restrict__ g, const float* __restrict__ be,
    float* __restrict__ Out, __half* __restrict__ Out16)
{
    __shared__ float red[8];
    const int row = blockIdx.x;
    const int tid = threadIdx.x;
    const float* xr = X + (size_t)row * DMODEL;
    const float* yr = Y + (size_t)row * DMODEL;

    float v[4];
    float s = 0.f;
#pragma unroll
    for (int c = 0; c < 4; c++) {
        const int idx = tid + 256 * c;
        v[c] = xr[idx] + yr[idx];
        s += v[c];
    }
#pragma unroll
    for (int off = 16; off >= 1; off >>= 1) s += __shfl_xor_sync(0xffffffffu, s, off);
    if ((tid & 31) == 0) red[tid >> 5] = s;
    __syncthreads();
    if (tid < 32) {
        float t = (tid < 8) ? red[tid] : 0.f;
#pragma unroll
        for (int off = 4; off >= 1; off >>= 1) t += __shfl_xor_sync(0xffffffffu, t, off);
        if (tid == 0) red[0] = t;
    }
    __syncthreads();
    const float mu = red[0] * (1.f / DMODEL);
    __syncthreads();

    float sq = 0.f;
#pragma unroll
    for (int c = 0; c < 4; c++) {
        const float d = v[c] - mu;
        sq += d * d;
    }
#pragma unroll
    for (int off = 16; off >= 1; off >>= 1) sq += __shfl_xor_sync(0xffffffffu, sq, off);
    if ((tid & 31) == 0) red[tid >> 5] = sq;
    __syncthreads();
    if (tid < 32) {
        float t = (tid < 8) ? red[tid] : 0.f;
#pragma unroll
        for (int off = 4; off >= 1; off >>= 1) t += __shfl_xor_sync(0xffffffffu, t, off);
        if (tid == 0) red[0] = t;
    }
    __syncthreads();
    const float rstd = rsqrtf(red[0] * (1.f / DMODEL) + 1e-5f);

    float* orow = Out + (size_t)row * DMODEL;
#pragma unroll
    for (int c = 0; c < 4; c++) {
        const int idx = tid + 256 * c;
        const float val = (v[c] - mu) * rstd * g[idx] + be[idx];
        orow[idx] = val;
        if (Out16) Out16[(size_t)row * DMODEL + idx] = __float2half(val);
    }
}

// =============================================================================
// Launch
// =============================================================================
extern "C" void kernel_launch(void* const* d_in, const int* in_sizes, int n_in,
                              void* d_out, int out_size)
{
    (void)in_sizes; (void)n_in; (void)out_size;
    const float* x     = (const float*)d_in[0];
    const float* enc   = (const float*)d_in[1];
    const float* Wq1 = (const float*)d_in[4];  const float* bq1 = (const float*)d_in[5];
    const float* Wk1 = (const float*)d_in[6];  const float* bk1 = (const float*)d_in[7];
    const float* Wv1 = (const float*)d_in[8];  const float* bv1 = (const float*)d_in[9];
    const float* Wo1 = (const float*)d_in[10]; const float* bo1 = (const float*)d_in[11];
    const float* Wq2 = (const float*)d_in[12]; const float* bq2 = (const float*)d_in[13];
    const float* Wk2 = (const float*)d_in[14]; const float* bk2 = (const float*)d_in[15];
    const float* Wv2 = (const float*)d_in[16]; const float* bv2 = (const float*)d_in[17];
    const float* Wo2 = (const float*)d_in[18]; const float* bo2 = (const float*)d_in[19];
    const float* Wf1 = (const float*)d_in[20]; const float* bf1 = (const float*)d_in[21];
    const float* Wf2 = (const float*)d_in[22]; const float* bf2 = (const float*)d_in[23];
    const float* g1  = (const float*)d_in[24]; const float* be1 = (const float*)d_in[25];
    const float* g2  = (const float*)d_in[26]; const float* be2 = (const float*)d_in[27];
    const float* g3  = (const float*)d_in[28]; const float* be3 = (const float*)d_in[29];
    float* out = (float*)d_out;

    float *o, *x1, *x2, *bqkv1, *bqkv2;
    __half *xh, *ench, *qkvh, *qkv2h, *ah, *x1h, *x2h, *ffh;
    __half *wqkv1h, *wqkv2h, *wo1h, *wo2h, *wf1h, *wf2h;
    cudaGetSymbolAddress((void**)&o,      g_o);
    cudaGetSymbolAddress((void**)&x1,     g_x1);
    cudaGetSymbolAddress((void**)&x2,     g_x2);
    cudaGetSymbolAddress((void**)&bqkv1,  g_bqkv1);
    cudaGetSymbolAddress((void**)&bqkv2,  g_bqkv2);
    cudaGetSymbolAddress((void**)&xh,     g_xh);
    cudaGetSymbolAddress((void**)&ench,   g_ench);
    cudaGetSymbolAddress((void**)&qkvh,   g_qkvh);
    cudaGetSymbolAddress((void**)&qkv2h,  g_qkv2h);
    cudaGetSymbolAddress((void**)&ah,     g_ah);
    cudaGetSymbolAddress((void**)&x1h,    g_x1h);
    cudaGetSymbolAddress((void**)&x2h,    g_x2h);
    cudaGetSymbolAddress((void**)&ffh,    g_ffh);
    cudaGetSymbolAddress((void**)&wqkv1h, g_wqkv1h);
    cudaGetSymbolAddress((void**)&wqkv2h, g_wqkv2h);
    cudaGetSymbolAddress((void**)&wo1h,   g_wo1h);
    cudaGetSymbolAddress((void**)&wo2h,   g_wo2h);
    cudaGetSymbolAddress((void**)&wf1h,   g_wf1h);
    cudaGetSymbolAddress((void**)&wf2h,   g_wf2h);

    // ---- conversions ----
    ConvTab tab;
    const int DD = DMODEL * DMODEL, DH = ROWS * DMODEL, DW = DFF * DMODEL;
    tab.e[0]  = {x,   xh,   DH, 1.f};
    tab.e[1]  = {enc, ench, DH, 1.f};
    tab.e[2]  = {Wq1, wqkv1h,          DD, 0.125f};   // 1/sqrt(64) folded
    tab.e[3]  = {Wk1, wqkv1h + DD,     DD, 1.f};
    tab.e[4]  = {Wv1, wqkv1h + 2 * DD, DD, 1.f};
    tab.e[5]  = {Wo1, wo1h, DD, 1.f};
    tab.e[6]  = {Wq2, wqkv2h,          DD, 0.125f};
    tab.e[7]  = {Wk2, wqkv2h + DD,     DD, 1.f};
    tab.e[8]  = {Wv2, wqkv2h + 2 * DD, DD, 1.f};
    tab.e[9]  = {Wo2, wo2h, DD, 1.f};
    tab.e[10] = {Wf1, wf1h, DW, 1.f};
    tab.e[11] = {Wf2, wf2h, DW, 1.f};
    conv_many<<<dim3(DW / (256 * 4), N_CONV), 256>>>(tab);
    bias_concat<<<12, 256>>>(bq1, bk1, bv1, bq2, bk2, bv2, bqkv1, bqkv2);

    const int FLASH_SMEM = (64 * FSH + 2 * KV_STG) * 2;      // 46080 B
    cudaFuncSetAttribute(flash_attn, cudaFuncAttributeMaxDynamicSharedMemorySize, FLASH_SMEM);
    const int GEMM_SMEM = 4 * GTILE * 2;                     // 73728 B
    cudaFuncSetAttribute(gemm_f16, cudaFuncAttributeMaxDynamicSharedMemorySize, GEMM_SMEM);
    cudaFuncSetAttribute(gemm_dual, cudaFuncAttributeMaxDynamicSharedMemorySize, GEMM_SMEM);

    const dim3 gProj(8, 32);                         // N=1024
    const dim3 gFF1 (32, 32);                        // N=4096
    const dim3 gDual(24 + 16, 32);                   // QKV1 (24) + KV2 (16)
    const dim3 gAttn(SEQ / 64, HEADS, BATCH);        // (32, 16, 2)
    const int LD3 = 3 * DMODEL;

    // ---- fused: self-attn QKV + cross-attn KV (both ready after conv) ----
    gemm_dual<<<gDual, 256, GEMM_SMEM>>>(
        xh,   wqkv1h,      bqkv1,          qkvh,
        ench, wqkv2h + DD, bqkv2 + DMODEL, qkv2h + DMODEL,
        24, DMODEL, LD3);

    // ---- self attention ----
    flash_attn<<<gAttn, 128, FLASH_SMEM>>>(qkvh, qkvh + DMODEL, qkvh + 2 * DMODEL, ah,
                                           SEQ, SEQ, LD3, LD3, 1);
    gemm_f16<<<gProj, 256, GEMM_SMEM>>>(ah, wo1h, bo1, o, nullptr, DMODEL, DMODEL, 0);
    add_ln<<<ROWS, 256>>>(x, o, g1, be1, x1, x1h);

    // ---- cross attention (K/V already in qkv2h) ----
    gemm_f16<<<gProj, 256, GEMM_SMEM>>>(x1h, wqkv2h, bqkv2, nullptr, qkv2h, DMODEL, LD3, 0);
    flash_attn<<<gAttn, 128, FLASH_SMEM>>>(qkv2h, qkv2h + DMODEL, qkv2h + 2 * DMODEL, ah,
                                           SEQ, SEQ, LD3, LD3, 0);
    gemm_f16<<<gProj, 256, GEMM_SMEM>>>(ah, wo2h, bo2, o, nullptr, DMODEL, DMODEL, 0);
    add_ln<<<ROWS, 256>>>(x1, o, g2, be2, x2, x2h);

    // ---- FFN ----
    gemm_f16<<<gFF1, 256, GEMM_SMEM>>>(x2h, wf1h, bf1, nullptr, ffh, DMODEL, DFF, 1);
    gemm_f16<<<gProj, 256, GEMM_SMEM>>>(ffh, wf2h, bf2, o, nullptr, DFF, DMODEL, 0);
    add_ln<<<ROWS, 256>>>(x2, o, g3, be3, out, nullptr);
}